// round 5
// baseline (speedup 1.0000x reference)
#include <cuda_runtime.h>
#include <math.h>
#include <stdint.h>

#define BB 8
#define NN 2048
#define DD 384
#define CP 64     // padded channel count (60 enc + 1 ones + 3 zero pad)
#define NF 10

// ---- scratch (device globals; no allocation allowed) ----
__device__ float g_pe[BB * CP * NN];   // pe' : (b, 64, N), ch60 = 1, ch61..63 = 0
__device__ float g_u [BB * CP * NN];   // u = M' pe'
__device__ float g_Z [BB * CP * NN];   // Z = pe' P^T / l
__device__ float g_M [CP * CP];        // sqrt(384)*[Wq|bq]^T[Wk|bk]; padding stays 0 (zero-init, never written)
__device__ float g_Wv[DD * CP];        // [Wv | bv | 0 0 0]

typedef unsigned long long ull;

__device__ __forceinline__ ull pk2(float lo, float hi) {
    ull d; asm("mov.b64 %0, {%1, %2};" : "=l"(d) : "f"(lo), "f"(hi)); return d;
}
__device__ __forceinline__ void upk2(ull v, float& lo, float& hi) {
    asm("mov.b64 {%0, %1}, %2;" : "=f"(lo), "=f"(hi) : "l"(v));
}
__device__ __forceinline__ ull fma2(ull a, ull b, ull c) {
    ull d; asm("fma.rn.f32x2 %0, %1, %2, %3;" : "=l"(d) : "l"(a), "l"(b), "l"(c)); return d;
}
__device__ __forceinline__ ull mul2(ull a, ull b) {
    ull d; asm("mul.rn.f32x2 %0, %1, %2;" : "=l"(d) : "l"(a), "l"(b)); return d;
}

// ---------------------------------------------------------------------------
// 1. positional encoding: pos (B,3,N) -> pe' (B,64,N)
// ---------------------------------------------------------------------------
__global__ void pe_kernel(const float* __restrict__ pos) {
    int idx = blockIdx.x * blockDim.x + threadIdx.x;
    if (idx >= BB * NN) return;
    int b = idx / NN, n = idx % NN;
    const float* p = pos + b * 3 * NN;
    float* pe = g_pe + b * CP * NN;
#pragma unroll
    for (int c = 0; c < 3; c++) {
        float v = p[c * NN + n];
        float f = 1.0f;
#pragma unroll
        for (int k = 0; k < NF; k++) {
            float s, co;
            sincosf(v * f, &s, &co);
            pe[(c * 2 * NF + k) * NN + n]      = s;
            pe[(c * 2 * NF + NF + k) * NN + n] = co;
            f *= 2.0f;
        }
    }
    pe[60 * NN + n] = 1.0f;
    pe[61 * NN + n] = 0.0f;
    pe[62 * NN + n] = 0.0f;
    pe[63 * NN + n] = 0.0f;
}

// ---------------------------------------------------------------------------
// 2. prep: warp-per-output for M' (61x61 dots of K=384), elementwise for Wv'
//    blocks [0, MBLK): M outputs;  blocks [MBLK, MBLK+WBLK): Wv copy
// ---------------------------------------------------------------------------
#define MOUT (61 * 61)
#define MBLK ((MOUT + 7) / 8)            // 8 warps per block
#define WBLK ((DD * CP + 255) / 256)

__global__ void __launch_bounds__(256) prep_kernel(
        const float* __restrict__ Wq, const float* __restrict__ bq,
        const float* __restrict__ Wk, const float* __restrict__ bk,
        const float* __restrict__ Wv, const float* __restrict__ bv) {
    int t = threadIdx.x;
    if (blockIdx.x < MBLK) {
        int w = blockIdx.x * 8 + (t >> 5);
        if (w >= MOUT) return;
        int i = w / 61, j = w % 61;
        int l = t & 31;
        float acc = 0.0f;
#pragma unroll
        for (int it = 0; it < 12; it++) {
            int d = l + it * 32;
            float aq = (i < 60) ? Wq[d * 60 + i] : bq[d];
            float ak = (j < 60) ? Wk[d * 60 + j] : bk[d];
            acc = fmaf(aq, ak, acc);
        }
#pragma unroll
        for (int s = 16; s > 0; s >>= 1)
            acc += __shfl_xor_sync(0xffffffffu, acc, s);
        if (l == 0) g_M[i * CP + j] = acc * sqrtf((float)DD);
    } else {
        int r = (blockIdx.x - MBLK) * 256 + t;
        if (r < DD * CP) {
            int d = r / CP, c = r % CP;
            g_Wv[r] = (c < 60) ? Wv[d * 60 + c] : ((c == 60) ? bv[d] : 0.0f);
        }
    }
}

// ---------------------------------------------------------------------------
// 3/5. small GEMM: Out[b, i0+i, n0+n] = sum_{c<64} A[i][c] * Bm[b][c][n]
// ---------------------------------------------------------------------------
__global__ void __launch_bounds__(256) gemm64_kernel(int mode, float* __restrict__ OutParam) {
    __shared__ float As[64][64];
    __shared__ float Bs[64][128];
    const float* A  = mode ? g_Wv : g_M;
    const float* Bm = mode ? g_Z  : g_pe;
    float* Out      = mode ? OutParam : g_u;
    const int I     = mode ? DD : CP;

    int b  = blockIdx.z;
    int i0 = blockIdx.y * 64;
    int n0 = blockIdx.x * 128;
    int t  = threadIdx.x;

    const float* Ap = A + i0 * CP;
#pragma unroll
    for (int j = 0; j < 4; j++) {
        int idx = t + j * 256;
        int row = idx >> 4, c4 = idx & 15;
        *reinterpret_cast<float4*>(&As[row][c4 * 4]) =
            *reinterpret_cast<const float4*>(Ap + row * CP + c4 * 4);
    }
    const float* Bp = Bm + b * CP * NN + n0;
#pragma unroll
    for (int j = 0; j < 8; j++) {
        int idx = t + j * 256;
        int row = idx >> 5, c4 = idx & 31;
        *reinterpret_cast<float4*>(&Bs[row][c4 * 4]) =
            *reinterpret_cast<const float4*>(Bp + row * NN + c4 * 4);
    }
    __syncthreads();

    int tx = t & 15, ty = t >> 4;
    float acc[4][8];
#pragma unroll
    for (int j = 0; j < 4; j++)
#pragma unroll
        for (int k = 0; k < 8; k++) acc[j][k] = 0.0f;

#pragma unroll 8
    for (int c = 0; c < 64; c++) {
        float a[4];
#pragma unroll
        for (int j = 0; j < 4; j++) a[j] = As[ty * 4 + j][c];
        float4 b0 = *reinterpret_cast<float4*>(&Bs[c][tx * 8]);
        float4 b1 = *reinterpret_cast<float4*>(&Bs[c][tx * 8 + 4]);
        float bb[8] = {b0.x, b0.y, b0.z, b0.w, b1.x, b1.y, b1.z, b1.w};
#pragma unroll
        for (int j = 0; j < 4; j++)
#pragma unroll
            for (int k = 0; k < 8; k++) acc[j][k] = fmaf(a[j], bb[k], acc[j][k]);
    }

    float* Op = Out + (size_t)b * I * NN + n0;
#pragma unroll
    for (int j = 0; j < 4; j++) {
        int i = i0 + ty * 4 + j;
        *reinterpret_cast<float4*>(Op + (size_t)i * NN + tx * 8) =
            make_float4(acc[j][0], acc[j][1], acc[j][2], acc[j][3]);
        *reinterpret_cast<float4*>(Op + (size_t)i * NN + tx * 8 + 4) =
            make_float4(acc[j][4], acc[j][5], acc[j][6], acc[j][7]);
    }
}

// ---------------------------------------------------------------------------
// 4. fused flash attention (512 threads, 4 rows/thread)
// ---------------------------------------------------------------------------
#define UP  140                    // Us pitch (swizzled: col -> col + (col>>5)*4)
#define PEP 76                     // PE (transposed pe m-tile) pitch: [m][c]
#define PMP 140                    // Pm pitch (same swizzle as Us)
#define OFF_AS 0
#define OFF_US (64 * 128)
#define OFF_PE (OFF_US + 64 * UP)
#define OFF_PM (OFF_PE + 128 * PEP)
#define SMEMF  (OFF_PM + 128 * PMP)   // 44800 floats = 179200 B

__global__ void __launch_bounds__(512, 1) fused_attn() {
    extern __shared__ float sm[];
    float* As = sm + OFF_AS;   // [64][128]  pe' n-tile (k-major)
    float* Us = sm + OFF_US;   // [64][UP]   u m-tile, column-swizzled
    float* PE = sm + OFF_PE;   // [128][PEP] pe' m-tile transposed: [m][c]
    float* Pm = sm + OFF_PM;   // [128][PMP] P tile, column-swizzled

    int b  = blockIdx.y;
    int n0 = blockIdx.x * 128;
    int t  = threadIdx.x;
    int tx = t & 15, tyy = t >> 4;           // tyy 0..31, 4 rows each
    int r0 = tyy * 4;
    int mph = tx * 8 + (tx >> 2) * 4;        // swizzled column base for m = 8*tx

    const float* peB = g_pe + b * CP * NN;
    const float* uB  = g_u  + b * CP * NN;

    // load A tile (pe' columns n0..n0+127), layout [c][n]
#pragma unroll
    for (int j = 0; j < 4; j++) {
        int idx = t + j * 512, row = idx >> 5, c4 = (idx & 31) * 4;
        *reinterpret_cast<float4*>(As + row * 128 + c4) =
            *reinterpret_cast<const float4*>(peB + row * NN + n0 + c4);
    }

    ull sacc[4][4];          // 4 rows x 4 m-pairs
    ull zacc[4][2];          // 4 rows x 2 c-pairs
    float mrun[4], lrun[4];
#pragma unroll
    for (int i = 0; i < 4; i++) {
        mrun[i] = -1e30f; lrun[i] = 0.0f; zacc[i][0] = 0ULL; zacc[i][1] = 0ULL;
    }

    for (int mt = 0; mt < 16; mt++) {
        int m0 = mt * 128;
        // fill Us (u tile, swizzled columns): 64x128
#pragma unroll
        for (int j = 0; j < 4; j++) {
            int idx = t + j * 512, row = idx >> 5, c4 = idx & 31;
            float4 v = *reinterpret_cast<const float4*>(uB + row * NN + m0 + c4 * 4);
            *reinterpret_cast<float4*>(Us + row * UP + c4 * 4 + (c4 >> 3) * 4) = v;
        }
        // fill PE transposed: PE[m][c] = pe'[c][m0+m]
#pragma unroll
        for (int j = 0; j < 16; j++) {
            int idx = t + j * 512, c = idx >> 7, m = idx & 127;
            PE[m * PEP + c] = peB[c * NN + m0 + m];
        }
        __syncthreads();

        // ---- GEMM1: S = A^T U (K=64) ----
#pragma unroll
        for (int i = 0; i < 4; i++) {
            sacc[i][0] = 0ULL; sacc[i][1] = 0ULL; sacc[i][2] = 0ULL; sacc[i][3] = 0ULL;
        }
#pragma unroll 4
        for (int k = 0; k < 64; k++) {
            float4 a0 = *reinterpret_cast<const float4*>(As + k * 128 + r0);
            ulonglong2 b01 = *reinterpret_cast<const ulonglong2*>(Us + k * UP + mph);
            ulonglong2 b23 = *reinterpret_cast<const ulonglong2*>(Us + k * UP + mph + 4);
            ull ad[4];
            ad[0] = pk2(a0.x, a0.x); ad[1] = pk2(a0.y, a0.y);
            ad[2] = pk2(a0.z, a0.z); ad[3] = pk2(a0.w, a0.w);
#pragma unroll
            for (int i = 0; i < 4; i++) {
                sacc[i][0] = fma2(ad[i], b01.x, sacc[i][0]);
                sacc[i][1] = fma2(ad[i], b01.y, sacc[i][1]);
                sacc[i][2] = fma2(ad[i], b23.x, sacc[i][2]);
                sacc[i][3] = fma2(ad[i], b23.y, sacc[i][3]);
            }
        }

        // ---- online softmax + write P tile ----
#pragma unroll
        for (int i = 0; i < 4; i++) {
            float s[8];
            upk2(sacc[i][0], s[0], s[1]); upk2(sacc[i][1], s[2], s[3]);
            upk2(sacc[i][2], s[4], s[5]); upk2(sacc[i][3], s[6], s[7]);
            float tm = fmaxf(fmaxf(fmaxf(s[0], s[1]), fmaxf(s[2], s[3])),
                             fmaxf(fmaxf(s[4], s[5]), fmaxf(s[6], s[7])));
            tm = fmaxf(tm, __shfl_xor_sync(0xffffffffu, tm, 8, 16));
            tm = fmaxf(tm, __shfl_xor_sync(0xffffffffu, tm, 4, 16));
            tm = fmaxf(tm, __shfl_xor_sync(0xffffffffu, tm, 2, 16));
            tm = fmaxf(tm, __shfl_xor_sync(0xffffffffu, tm, 1, 16));
            float nm = fmaxf(mrun[i], tm);
            float al = __expf(mrun[i] - nm);
            mrun[i] = nm;
            float p[8], rs = 0.0f;
#pragma unroll
            for (int j = 0; j < 8; j++) { p[j] = __expf(s[j] - nm); rs += p[j]; }
            lrun[i] = fmaf(lrun[i], al, rs);
            ull a2 = pk2(al, al);
            zacc[i][0] = mul2(zacc[i][0], a2);
            zacc[i][1] = mul2(zacc[i][1], a2);
            *reinterpret_cast<float4*>(Pm + (r0 + i) * PMP + mph) =
                make_float4(p[0], p[1], p[2], p[3]);
            *reinterpret_cast<float4*>(Pm + (r0 + i) * PMP + mph + 4) =
                make_float4(p[4], p[5], p[6], p[7]);
        }
        __syncthreads();

        // ---- GEMM2: Z[n][c] += sum_m P[n][m] pe'[c][m] ----
#pragma unroll 2
        for (int mc = 0; mc < 128; mc += 4) {
            int mcp = mc + (mc >> 5) * 4;    // swizzled Pm column
            ulonglong2 q0 = *reinterpret_cast<const ulonglong2*>(PE + (mc + 0) * PEP + tx * 4);
            ulonglong2 q1 = *reinterpret_cast<const ulonglong2*>(PE + (mc + 1) * PEP + tx * 4);
            ulonglong2 q2 = *reinterpret_cast<const ulonglong2*>(PE + (mc + 2) * PEP + tx * 4);
            ulonglong2 q3 = *reinterpret_cast<const ulonglong2*>(PE + (mc + 3) * PEP + tx * 4);
#pragma unroll
            for (int i = 0; i < 4; i++) {
                float4 pv = *reinterpret_cast<const float4*>(Pm + (r0 + i) * PMP + mcp);
                ull d0 = pk2(pv.x, pv.x), d1 = pk2(pv.y, pv.y);
                ull d2 = pk2(pv.z, pv.z), d3 = pk2(pv.w, pv.w);
                zacc[i][0] = fma2(d0, q0.x, zacc[i][0]);
                zacc[i][1] = fma2(d0, q0.y, zacc[i][1]);
                zacc[i][0] = fma2(d1, q1.x, zacc[i][0]);
                zacc[i][1] = fma2(d1, q1.y, zacc[i][1]);
                zacc[i][0] = fma2(d2, q2.x, zacc[i][0]);
                zacc[i][1] = fma2(d2, q2.y, zacc[i][1]);
                zacc[i][0] = fma2(d3, q3.x, zacc[i][0]);
                zacc[i][1] = fma2(d3, q3.y, zacc[i][1]);
            }
        }
        __syncthreads();
    }

    // ---- epilogue: reduce l across the 16 tx lanes, normalize, write Z ----
#pragma unroll
    for (int i = 0; i < 4; i++) {
        float l = lrun[i];
        l += __shfl_xor_sync(0xffffffffu, l, 8, 16);
        l += __shfl_xor_sync(0xffffffffu, l, 4, 16);
        l += __shfl_xor_sync(0xffffffffu, l, 2, 16);
        l += __shfl_xor_sync(0xffffffffu, l, 1, 16);
        lrun[i] = l;
    }
    float* Zb = g_Z + b * CP * NN;
#pragma unroll
    for (int i = 0; i < 4; i++) {
        float inv = 1.0f / lrun[i];
        float z0, z1, z2, z3;
        upk2(zacc[i][0], z0, z1);
        upk2(zacc[i][1], z2, z3);
        int n = n0 + r0 + i;
        Zb[(tx * 4 + 0) * NN + n] = z0 * inv;
        Zb[(tx * 4 + 1) * NN + n] = z1 * inv;
        Zb[(tx * 4 + 2) * NN + n] = z2 * inv;
        Zb[(tx * 4 + 3) * NN + n] = z3 * inv;
    }
}

// ---------------------------------------------------------------------------
extern "C" void kernel_launch(void* const* d_in, const int* in_sizes, int n_in,
                              void* d_out, int out_size) {
    const float* pos = (const float*)d_in[0];
    const float* Wq  = (const float*)d_in[1];
    const float* bq  = (const float*)d_in[2];
    const float* Wk  = (const float*)d_in[3];
    const float* bk  = (const float*)d_in[4];
    const float* Wv  = (const float*)d_in[5];
    const float* bv  = (const float*)d_in[6];
    float* out = (float*)d_out;

    pe_kernel<<<(BB * NN + 255) / 256, 256>>>(pos);
    prep_kernel<<<MBLK + WBLK, 256>>>(Wq, bq, Wk, bk, Wv, bv);

    // u = M' pe'
    gemm64_kernel<<<dim3(NN / 128, 1, BB), 256>>>(0, nullptr);

    // fused S -> softmax -> Z
    cudaFuncSetAttribute(fused_attn, cudaFuncAttributeMaxDynamicSharedMemorySize,
                         SMEMF * (int)sizeof(float));
    fused_attn<<<dim3(NN / 128, BB), 512, SMEMF * sizeof(float)>>>();

    // out = Wv' Z
    gemm64_kernel<<<dim3(NN / 128, DD / 64, BB), 256>>>(1, out);
}

// round 7
// speedup vs baseline: 1.8556x; 1.8556x over previous
#include <cuda_runtime.h>
#include <cuda_bf16.h>
#include <math.h>
#include <stdint.h>

#define BB 8
#define NN 2048
#define DD 384
#define CP 64
#define NF 10

__device__ float g_pe[BB * CP * NN];   // pe' (b, 64, N)
__device__ float g_u [BB * CP * NN];   // u = M' pe'
__device__ float g_Z [BB * CP * NN];   // Z = pe' P^T / l
__device__ float g_M [CP * CP];        // padding stays 0 (zero-init, never written)
__device__ float g_Wv[DD * CP];
__device__ __nv_bfloat16 g_An_hi[BB * NN * CP];  // pe' transposed [b][n][c]
__device__ __nv_bfloat16 g_An_lo[BB * NN * CP];
__device__ __nv_bfloat16 g_U_hi [BB * NN * CP];  // u transposed [b][m][c]
__device__ __nv_bfloat16 g_U_lo [BB * NN * CP];
__device__ __nv_bfloat16 g_Bk_hi[BB * CP * NN];  // pe' natural [b][c][m]
__device__ __nv_bfloat16 g_Bk_lo[BB * CP * NN];

// ---------------- 1. positional encoding ----------------
__global__ void pe_kernel(const float* __restrict__ pos) {
    int idx = blockIdx.x * blockDim.x + threadIdx.x;
    if (idx >= BB * NN) return;
    int b = idx / NN, n = idx % NN;
    const float* p = pos + b * 3 * NN;
    float* pe = g_pe + b * CP * NN;
#pragma unroll
    for (int c = 0; c < 3; c++) {
        float v = p[c * NN + n];
        float f = 1.0f;
#pragma unroll
        for (int k = 0; k < NF; k++) {
            float s, co;
            sincosf(v * f, &s, &co);
            pe[(c * 2 * NF + k) * NN + n]      = s;
            pe[(c * 2 * NF + NF + k) * NN + n] = co;
            f *= 2.0f;
        }
    }
    pe[60 * NN + n] = 1.0f;
    pe[61 * NN + n] = 0.0f;
    pe[62 * NN + n] = 0.0f;
    pe[63 * NN + n] = 0.0f;
}

// ---------------- 2. prep ----------------
#define MOUT (61 * 61)
#define MBLK ((MOUT + 7) / 8)
#define WBLK ((DD * CP + 255) / 256)
__global__ void __launch_bounds__(256) prep_kernel(
        const float* __restrict__ Wq, const float* __restrict__ bq,
        const float* __restrict__ Wk, const float* __restrict__ bk,
        const float* __restrict__ Wv, const float* __restrict__ bv) {
    int t = threadIdx.x;
    if (blockIdx.x < MBLK) {
        int w = blockIdx.x * 8 + (t >> 5);
        if (w >= MOUT) return;
        int i = w / 61, j = w % 61, l = t & 31;
        float acc = 0.0f;
#pragma unroll
        for (int it = 0; it < 12; it++) {
            int d = l + it * 32;
            float aq = (i < 60) ? Wq[d * 60 + i] : bq[d];
            float ak = (j < 60) ? Wk[d * 60 + j] : bk[d];
            acc = fmaf(aq, ak, acc);
        }
#pragma unroll
        for (int s = 16; s > 0; s >>= 1) acc += __shfl_xor_sync(0xffffffffu, acc, s);
        if (l == 0) g_M[i * CP + j] = acc * sqrtf((float)DD);
    } else {
        int r = (blockIdx.x - MBLK) * 256 + t;
        if (r < DD * CP) {
            int d = r / CP, c = r % CP;
            g_Wv[r] = (c < 60) ? Wv[d * 60 + c] : ((c == 60) ? bv[d] : 0.0f);
        }
    }
}

// ---------------- 3. small GEMM (mode 0: u = M' pe'; mode 1: out = Wv' Z) ----------------
__global__ void __launch_bounds__(256) gemm64_kernel(int mode, float* __restrict__ OutParam) {
    __shared__ float As[64][64];
    __shared__ float Bs[64][128];
    const float* A  = mode ? g_Wv : g_M;
    const float* Bm = mode ? g_Z  : g_pe;
    float* Out      = mode ? OutParam : g_u;
    const int I     = mode ? DD : CP;
    int b = blockIdx.z, i0 = blockIdx.y * 64, n0 = blockIdx.x * 128, t = threadIdx.x;
    const float* Ap = A + i0 * CP;
#pragma unroll
    for (int j = 0; j < 4; j++) {
        int idx = t + j * 256, row = idx >> 4, c4 = idx & 15;
        *reinterpret_cast<float4*>(&As[row][c4 * 4]) =
            *reinterpret_cast<const float4*>(Ap + row * CP + c4 * 4);
    }
    const float* Bp = Bm + b * CP * NN + n0;
#pragma unroll
    for (int j = 0; j < 8; j++) {
        int idx = t + j * 256, row = idx >> 5, c4 = idx & 31;
        *reinterpret_cast<float4*>(&Bs[row][c4 * 4]) =
            *reinterpret_cast<const float4*>(Bp + row * NN + c4 * 4);
    }
    __syncthreads();
    int tx = t & 15, ty = t >> 4;
    float acc[4][8];
#pragma unroll
    for (int j = 0; j < 4; j++)
#pragma unroll
        for (int k = 0; k < 8; k++) acc[j][k] = 0.0f;
#pragma unroll 8
    for (int c = 0; c < 64; c++) {
        float a[4];
#pragma unroll
        for (int j = 0; j < 4; j++) a[j] = As[ty * 4 + j][c];
        float4 b0 = *reinterpret_cast<float4*>(&Bs[c][tx * 8]);
        float4 b1 = *reinterpret_cast<float4*>(&Bs[c][tx * 8 + 4]);
        float bb[8] = {b0.x, b0.y, b0.z, b0.w, b1.x, b1.y, b1.z, b1.w};
#pragma unroll
        for (int j = 0; j < 4; j++)
#pragma unroll
            for (int k = 0; k < 8; k++) acc[j][k] = fmaf(a[j], bb[k], acc[j][k]);
    }
    float* Op = Out + (size_t)b * I * NN + n0;
#pragma unroll
    for (int j = 0; j < 4; j++) {
        int i = i0 + ty * 4 + j;
        *reinterpret_cast<float4*>(Op + (size_t)i * NN + tx * 8) =
            make_float4(acc[j][0], acc[j][1], acc[j][2], acc[j][3]);
        *reinterpret_cast<float4*>(Op + (size_t)i * NN + tx * 8 + 4) =
            make_float4(acc[j][4], acc[j][5], acc[j][6], acc[j][7]);
    }
}

// ---------------- 4a. split+transpose [c][n] -> [n][c] hi/lo ----------------
__global__ void __launch_bounds__(256) split_tr(int mode) {
    __shared__ float buf[64][129];
    int b = blockIdx.y, n0 = blockIdx.x * 128, t = threadIdx.x;
    const float* src = (mode ? g_u : g_pe) + (size_t)b * CP * NN;
    __nv_bfloat16* dh = (mode ? g_U_hi : g_An_hi) + ((size_t)b * NN + n0) * CP;
    __nv_bfloat16* dl = (mode ? g_U_lo : g_An_lo) + ((size_t)b * NN + n0) * CP;
#pragma unroll
    for (int j = 0; j < 32; j++) {
        int idx = t + j * 256, c = idx >> 7, n = idx & 127;
        buf[c][n] = src[c * NN + n0 + n];
    }
    __syncthreads();
#pragma unroll
    for (int j = 0; j < 32; j++) {
        int idx = t + j * 256, n = idx >> 6, c = idx & 63;
        float x = buf[c][n];
        __nv_bfloat16 h = __float2bfloat16(x);
        dh[n * CP + c] = h;
        dl[n * CP + c] = __float2bfloat16(x - __bfloat162float(h));
    }
}
// 4b. elementwise split pe -> Bk hi/lo
__global__ void __launch_bounds__(256) split_bk() {
    int idx = blockIdx.x * blockDim.x + threadIdx.x;
    if (idx >= BB * CP * NN) return;
    float x = g_pe[idx];
    __nv_bfloat16 h = __float2bfloat16(x);
    g_Bk_hi[idx] = h;
    g_Bk_lo[idx] = __float2bfloat16(x - __bfloat162float(h));
}

// ---------------- 5. mma.sync fused flash attention ----------------
#define PITA 144                 // byte pitch for [.][c] tiles (64 bf16 + 8 pad)
#define PITK 272                 // byte pitch for K [c][m] tiles (128 bf16 + 8 pad)
#define SM_APEH 0
#define SM_APEL 18432
#define SM_UH   36864
#define SM_UL   55296
#define SM_KH   73728
#define SM_KL   91136
#define SM_TOT  108544

__device__ __forceinline__ void mma16816(float* d, const uint32_t* a, const uint32_t* b) {
    asm volatile("mma.sync.aligned.m16n8k16.row.col.f32.bf16.bf16.f32 "
        "{%0,%1,%2,%3}, {%4,%5,%6,%7}, {%8,%9}, {%0,%1,%2,%3};"
        : "+f"(d[0]), "+f"(d[1]), "+f"(d[2]), "+f"(d[3])
        : "r"(a[0]), "r"(a[1]), "r"(a[2]), "r"(a[3]), "r"(b[0]), "r"(b[1]));
}
__device__ __forceinline__ uint32_t pkbf(float lo, float hi) {
    __nv_bfloat16 h0 = __float2bfloat16(lo), h1 = __float2bfloat16(hi);
    return ((uint32_t)__bfloat16_as_ushort(h1) << 16) | __bfloat16_as_ushort(h0);
}

__global__ void __launch_bounds__(256, 1) fused_attn_mma() {
    extern __shared__ char smc[];
    const int t = threadIdx.x, w = t >> 5, lane = t & 31;
    const int g = lane >> 2, tg = lane & 3;
    const int b = blockIdx.y, n0 = blockIdx.x * 128;

    // fill APE hi/lo: [n][c] rows of 128B into pitch-144 rows
    {
        const float4* sh = (const float4*)(g_An_hi + ((size_t)b * NN + n0) * CP);
        const float4* sl = (const float4*)(g_An_lo + ((size_t)b * NN + n0) * CP);
#pragma unroll
        for (int j = 0; j < 4; j++) {
            int li = t + j * 256, row = li >> 3, ch = li & 7;
            *(float4*)(smc + SM_APEH + row * PITA + ch * 16) = sh[li];
            *(float4*)(smc + SM_APEL + row * PITA + ch * 16) = sl[li];
        }
    }

    float zacc[8][4];
#pragma unroll
    for (int cf = 0; cf < 8; cf++)
#pragma unroll
        for (int e = 0; e < 4; e++) zacc[cf][e] = 0.0f;
    float mrun0 = -1e30f, mrun1 = -1e30f, lrun0 = 0.0f, lrun1 = 0.0f;

    for (int mt = 0; mt < 16; mt++) {
        int m0 = mt * 128;
        // fill U hi/lo [m][c]
        {
            const float4* sh = (const float4*)(g_U_hi + ((size_t)b * NN + m0) * CP);
            const float4* sl = (const float4*)(g_U_lo + ((size_t)b * NN + m0) * CP);
#pragma unroll
            for (int j = 0; j < 4; j++) {
                int li = t + j * 256, row = li >> 3, ch = li & 7;
                *(float4*)(smc + SM_UH + row * PITA + ch * 16) = sh[li];
                *(float4*)(smc + SM_UL + row * PITA + ch * 16) = sl[li];
            }
        }
        // fill K hi/lo [c][m]
        {
#pragma unroll
            for (int j = 0; j < 4; j++) {
                int li = t + j * 256, row = li >> 4, ch = li & 15;
                const float4* sh = (const float4*)(g_Bk_hi + (size_t)(b * CP + row) * NN + m0);
                const float4* sl = (const float4*)(g_Bk_lo + (size_t)(b * CP + row) * NN + m0);
                *(float4*)(smc + SM_KH + row * PITK + ch * 16) = sh[ch];
                *(float4*)(smc + SM_KL + row * PITK + ch * 16) = sl[ch];
            }
        }
        __syncthreads();

        // ---- S = APE * U^T (3-term split), per warp 16 rows x 128 cols ----
        float sfr[16][4];
#pragma unroll
        for (int mf = 0; mf < 16; mf++)
#pragma unroll
            for (int e = 0; e < 4; e++) sfr[mf][e] = 0.0f;

#pragma unroll
        for (int ks = 0; ks < 4; ks++) {
            uint32_t abase = (uint32_t)((w * 16 + g) * PITA + (ks * 16 + tg * 2) * 2);
            uint32_t ah[4], al_[4];
            ah[0]  = *(const uint32_t*)(smc + SM_APEH + abase);
            ah[1]  = *(const uint32_t*)(smc + SM_APEH + abase + 8 * PITA);
            ah[2]  = *(const uint32_t*)(smc + SM_APEH + abase + 16);
            ah[3]  = *(const uint32_t*)(smc + SM_APEH + abase + 8 * PITA + 16);
            al_[0] = *(const uint32_t*)(smc + SM_APEL + abase);
            al_[1] = *(const uint32_t*)(smc + SM_APEL + abase + 8 * PITA);
            al_[2] = *(const uint32_t*)(smc + SM_APEL + abase + 16);
            al_[3] = *(const uint32_t*)(smc + SM_APEL + abase + 8 * PITA + 16);
#pragma unroll
            for (int mf = 0; mf < 16; mf++) {
                uint32_t bbase = (uint32_t)((mf * 8 + g) * PITA + (ks * 16 + tg * 2) * 2);
                uint32_t bh[2] = { *(const uint32_t*)(smc + SM_UH + bbase),
                                   *(const uint32_t*)(smc + SM_UH + bbase + 16) };
                uint32_t bl[2] = { *(const uint32_t*)(smc + SM_UL + bbase),
                                   *(const uint32_t*)(smc + SM_UL + bbase + 16) };
                mma16816(sfr[mf], ah, bh);
                mma16816(sfr[mf], ah, bl);
                mma16816(sfr[mf], al_, bh);
            }
        }

        // ---- online softmax (rows g and g+8 of this warp) ----
        float tm0 = -1e30f, tm1 = -1e30f;
#pragma unroll
        for (int mf = 0; mf < 16; mf++) {
            tm0 = fmaxf(tm0, fmaxf(sfr[mf][0], sfr[mf][1]));
            tm1 = fmaxf(tm1, fmaxf(sfr[mf][2], sfr[mf][3]));
        }
        tm0 = fmaxf(tm0, __shfl_xor_sync(0xffffffffu, tm0, 1));
        tm0 = fmaxf(tm0, __shfl_xor_sync(0xffffffffu, tm0, 2));
        tm1 = fmaxf(tm1, __shfl_xor_sync(0xffffffffu, tm1, 1));
        tm1 = fmaxf(tm1, __shfl_xor_sync(0xffffffffu, tm1, 2));
        float nm0 = fmaxf(mrun0, tm0), nm1 = fmaxf(mrun1, tm1);
        float al0 = __expf(mrun0 - nm0), al1 = __expf(mrun1 - nm1);
        mrun0 = nm0; mrun1 = nm1;
#pragma unroll
        for (int cf = 0; cf < 8; cf++) {
            zacc[cf][0] *= al0; zacc[cf][1] *= al0;
            zacc[cf][2] *= al1; zacc[cf][3] *= al1;
        }
        lrun0 *= al0; lrun1 *= al1;

        uint32_t ph[16][2], pl[16][2];
        float rs0 = 0.0f, rs1 = 0.0f;
#pragma unroll
        for (int mf = 0; mf < 16; mf++) {
            float p0 = __expf(sfr[mf][0] - nm0), p1 = __expf(sfr[mf][1] - nm0);
            float p2 = __expf(sfr[mf][2] - nm1), p3 = __expf(sfr[mf][3] - nm1);
            rs0 += p0 + p1; rs1 += p2 + p3;
            ph[mf][0] = pkbf(p0, p1);
            ph[mf][1] = pkbf(p2, p3);
            float q0 = p0 - __bfloat162float(__float2bfloat16(p0));
            float q1 = p1 - __bfloat162float(__float2bfloat16(p1));
            float q2 = p2 - __bfloat162float(__float2bfloat16(p2));
            float q3 = p3 - __bfloat162float(__float2bfloat16(p3));
            pl[mf][0] = pkbf(q0, q1);
            pl[mf][1] = pkbf(q2, q3);
        }
        rs0 += __shfl_xor_sync(0xffffffffu, rs0, 1);
        rs0 += __shfl_xor_sync(0xffffffffu, rs0, 2);
        rs1 += __shfl_xor_sync(0xffffffffu, rs1, 1);
        rs1 += __shfl_xor_sync(0xffffffffu, rs1, 2);
        lrun0 += rs0; lrun1 += rs1;

        // ---- Z += P * K^T (3-term split), K-dim = m (128) ----
#pragma unroll
        for (int ks = 0; ks < 8; ks++) {
            uint32_t aph[4] = { ph[2 * ks][0], ph[2 * ks][1], ph[2 * ks + 1][0], ph[2 * ks + 1][1] };
            uint32_t apl[4] = { pl[2 * ks][0], pl[2 * ks][1], pl[2 * ks + 1][0], pl[2 * ks + 1][1] };
#pragma unroll
            for (int cf = 0; cf < 8; cf++) {
                uint32_t bb = (uint32_t)((cf * 8 + g) * PITK + (ks * 16 + tg * 2) * 2);
                uint32_t kh[2] = { *(const uint32_t*)(smc + SM_KH + bb),
                                   *(const uint32_t*)(smc + SM_KH + bb + 16) };
                uint32_t kl[2] = { *(const uint32_t*)(smc + SM_KL + bb),
                                   *(const uint32_t*)(smc + SM_KL + bb + 16) };
                mma16816(zacc[cf], aph, kh);
                mma16816(zacc[cf], apl, kh);
                mma16816(zacc[cf], aph, kl);
            }
        }
        __syncthreads();
    }

    // ---- epilogue: normalize, write g_Z [c][n] ----
    float inv0 = 1.0f / lrun0, inv1 = 1.0f / lrun1;
    int nl0 = n0 + w * 16 + g, nl1 = nl0 + 8;
    float* Zb = g_Z + (size_t)b * CP * NN;
#pragma unroll
    for (int cf = 0; cf < 8; cf++) {
        int c0 = cf * 8 + tg * 2;
        Zb[(size_t)c0 * NN + nl0]       = zacc[cf][0] * inv0;
        Zb[(size_t)(c0 + 1) * NN + nl0] = zacc[cf][1] * inv0;
        Zb[(size_t)c0 * NN + nl1]       = zacc[cf][2] * inv1;
        Zb[(size_t)(c0 + 1) * NN + nl1] = zacc[cf][3] * inv1;
    }
}

// ---------------------------------------------------------------------------
extern "C" void kernel_launch(void* const* d_in, const int* in_sizes, int n_in,
                              void* d_out, int out_size) {
    const float* pos = (const float*)d_in[0];
    const float* Wq  = (const float*)d_in[1];
    const float* bq  = (const float*)d_in[2];
    const float* Wk  = (const float*)d_in[3];
    const float* bk  = (const float*)d_in[4];
    const float* Wv  = (const float*)d_in[5];
    const float* bv  = (const float*)d_in[6];
    float* out = (float*)d_out;

    pe_kernel<<<(BB * NN + 255) / 256, 256>>>(pos);
    prep_kernel<<<MBLK + WBLK, 256>>>(Wq, bq, Wk, bk, Wv, bv);
    gemm64_kernel<<<dim3(NN / 128, 1, BB), 256>>>(0, nullptr);   // u = M' pe'

    split_tr<<<dim3(NN / 128, BB), 256>>>(0);                    // pe -> An hi/lo
    split_tr<<<dim3(NN / 128, BB), 256>>>(1);                    // u  -> U  hi/lo
    split_bk<<<(BB * CP * NN + 255) / 256, 256>>>();             // pe -> Bk hi/lo

    cudaFuncSetAttribute(fused_attn_mma, cudaFuncAttributeMaxDynamicSharedMemorySize, SM_TOT);
    fused_attn_mma<<<dim3(NN / 128, BB), 256, SM_TOT>>>();

    gemm64_kernel<<<dim3(NN / 128, DD / 64, BB), 256>>>(1, out); // out = Wv' Z
}

// round 8
// speedup vs baseline: 1.9833x; 1.0688x over previous
#include <cuda_runtime.h>
#include <cuda_bf16.h>
#include <math.h>
#include <stdint.h>

#define BB 8
#define NN 2048
#define DD 384
#define CP 64
#define NF 10

__device__ float g_pe[BB * CP * NN];   // pe' (b, 64, N)
__device__ float g_Z [BB * CP * NN];   // Z = pe' P^T / l
__device__ float g_M [CP * CP];        // padding stays 0 (zero-init, never written)
__device__ float g_Wv[DD * CP];
__device__ __nv_bfloat16 g_An_hi[BB * NN * CP];  // pe' transposed [b][n][c]
__device__ __nv_bfloat16 g_An_lo[BB * NN * CP];
__device__ __nv_bfloat16 g_U_hi [BB * NN * CP];  // u transposed [b][m][c]
__device__ __nv_bfloat16 g_U_lo [BB * NN * CP];
__device__ __nv_bfloat16 g_Bk_hi[BB * CP * NN];  // pe' natural [b][c][m]
__device__ __nv_bfloat16 g_Bk_lo[BB * CP * NN];

__device__ __forceinline__ uint32_t smem_u32(const void* p) {
    uint32_t a;
    asm("{ .reg .u64 t; cvta.to.shared.u64 t, %1; cvt.u32.u64 %0, t; }" : "=r"(a) : "l"(p));
    return a;
}
__device__ __forceinline__ void cp16(uint32_t dst, const void* src) {
    asm volatile("cp.async.cg.shared.global [%0], [%1], 16;" :: "r"(dst), "l"(src));
}
#define CP_COMMIT() asm volatile("cp.async.commit_group;" ::: "memory")
#define CP_WAIT1()  asm volatile("cp.async.wait_group 1;" ::: "memory")
#define CP_WAIT0()  asm volatile("cp.async.wait_group 0;" ::: "memory")

// ---------------- 1. positional encoding + bf16 splits ----------------
__global__ void __launch_bounds__(256) pe_kernel(const float* __restrict__ pos) {
    int idx = blockIdx.x * blockDim.x + threadIdx.x;
    if (idx >= BB * NN) return;
    int b = idx / NN, n = idx % NN;
    const float* p = pos + b * 3 * NN;
    float v[64];
#pragma unroll
    for (int c = 0; c < 3; c++) {
        float x = p[c * NN + n];
        float f = 1.0f;
#pragma unroll
        for (int k = 0; k < NF; k++) {
            float s, co;
            sincosf(x * f, &s, &co);
            v[c * 2 * NF + k]      = s;
            v[c * 2 * NF + NF + k] = co;
            f *= 2.0f;
        }
    }
    v[60] = 1.0f; v[61] = 0.0f; v[62] = 0.0f; v[63] = 0.0f;

    float* pe = g_pe + (size_t)b * CP * NN + n;
    __nv_bfloat16* bkh = g_Bk_hi + (size_t)b * CP * NN + n;
    __nv_bfloat16* bkl = g_Bk_lo + (size_t)b * CP * NN + n;
    __nv_bfloat16 hi[64], lo[64];
#pragma unroll
    for (int c = 0; c < 64; c++) {
        pe[(size_t)c * NN] = v[c];
        __nv_bfloat16 h = __float2bfloat16(v[c]);
        __nv_bfloat16 l = __float2bfloat16(v[c] - __bfloat162float(h));
        hi[c] = h; lo[c] = l;
        bkh[(size_t)c * NN] = h;
        bkl[(size_t)c * NN] = l;
    }
    float4* dh = (float4*)(g_An_hi + ((size_t)b * NN + n) * CP);
    float4* dl = (float4*)(g_An_lo + ((size_t)b * NN + n) * CP);
#pragma unroll
    for (int j = 0; j < 8; j++) {
        dh[j] = ((float4*)hi)[j];
        dl[j] = ((float4*)lo)[j];
    }
}

// ---------------- 2. prep ----------------
#define MOUT (61 * 61)
#define MBLK ((MOUT + 7) / 8)
#define WBLK ((DD * CP + 255) / 256)
__global__ void __launch_bounds__(256) prep_kernel(
        const float* __restrict__ Wq, const float* __restrict__ bq,
        const float* __restrict__ Wk, const float* __restrict__ bk,
        const float* __restrict__ Wv, const float* __restrict__ bv) {
    int t = threadIdx.x;
    if (blockIdx.x < MBLK) {
        int w = blockIdx.x * 8 + (t >> 5);
        if (w >= MOUT) return;
        int i = w / 61, j = w % 61, l = t & 31;
        float acc = 0.0f;
#pragma unroll
        for (int it = 0; it < 12; it++) {
            int d = l + it * 32;
            float aq = (i < 60) ? Wq[d * 60 + i] : bq[d];
            float ak = (j < 60) ? Wk[d * 60 + j] : bk[d];
            acc = fmaf(aq, ak, acc);
        }
#pragma unroll
        for (int s = 16; s > 0; s >>= 1) acc += __shfl_xor_sync(0xffffffffu, acc, s);
        if (l == 0) g_M[i * CP + j] = acc * sqrtf((float)DD);
    } else {
        int r = (blockIdx.x - MBLK) * 256 + t;
        if (r < DD * CP) {
            int d = r / CP, c = r % CP;
            g_Wv[r] = (c < 60) ? Wv[d * 60 + c] : ((c == 60) ? bv[d] : 0.0f);
        }
    }
}

// ---------------- 3a. u = M' pe', written directly as split bf16 [m][c] ----------------
__global__ void __launch_bounds__(256) gemm_u_kernel() {
    __shared__ float As[64][64];
    __shared__ float Bs[64][128];
    int b = blockIdx.z, n0 = blockIdx.x * 128, t = threadIdx.x;
#pragma unroll
    for (int j = 0; j < 4; j++) {
        int idx = t + j * 256, row = idx >> 4, c4 = idx & 15;
        *reinterpret_cast<float4*>(&As[row][c4 * 4]) =
            *reinterpret_cast<const float4*>(g_M + row * CP + c4 * 4);
    }
    const float* Bp = g_pe + (size_t)b * CP * NN + n0;
#pragma unroll
    for (int j = 0; j < 8; j++) {
        int idx = t + j * 256, row = idx >> 5, c4 = idx & 31;
        *reinterpret_cast<float4*>(&Bs[row][c4 * 4]) =
            *reinterpret_cast<const float4*>(Bp + row * NN + c4 * 4);
    }
    __syncthreads();
    int tx = t & 15, ty = t >> 4;
    float acc[4][8];
#pragma unroll
    for (int j = 0; j < 4; j++)
#pragma unroll
        for (int k = 0; k < 8; k++) acc[j][k] = 0.0f;
#pragma unroll 8
    for (int c = 0; c < 64; c++) {
        float a[4];
#pragma unroll
        for (int j = 0; j < 4; j++) a[j] = As[ty * 4 + j][c];
        float4 b0 = *reinterpret_cast<float4*>(&Bs[c][tx * 8]);
        float4 b1 = *reinterpret_cast<float4*>(&Bs[c][tx * 8 + 4]);
        float bb[8] = {b0.x, b0.y, b0.z, b0.w, b1.x, b1.y, b1.z, b1.w};
#pragma unroll
        for (int j = 0; j < 4; j++)
#pragma unroll
            for (int k = 0; k < 8; k++) acc[j][k] = fmaf(a[j], bb[k], acc[j][k]);
    }
#pragma unroll
    for (int k = 0; k < 8; k++) {
        size_t m = (size_t)b * NN + n0 + tx * 8 + k;
        ushort4 hv, lv;
        __nv_bfloat16 h;
        h = __float2bfloat16(acc[0][k]); hv.x = __bfloat16_as_ushort(h);
        lv.x = __bfloat16_as_ushort(__float2bfloat16(acc[0][k] - __bfloat162float(h)));
        h = __float2bfloat16(acc[1][k]); hv.y = __bfloat16_as_ushort(h);
        lv.y = __bfloat16_as_ushort(__float2bfloat16(acc[1][k] - __bfloat162float(h)));
        h = __float2bfloat16(acc[2][k]); hv.z = __bfloat16_as_ushort(h);
        lv.z = __bfloat16_as_ushort(__float2bfloat16(acc[2][k] - __bfloat162float(h)));
        h = __float2bfloat16(acc[3][k]); hv.w = __bfloat16_as_ushort(h);
        lv.w = __bfloat16_as_ushort(__float2bfloat16(acc[3][k] - __bfloat162float(h)));
        *reinterpret_cast<ushort4*>(g_U_hi + m * CP + ty * 4) = hv;
        *reinterpret_cast<ushort4*>(g_U_lo + m * CP + ty * 4) = lv;
    }
}

// ---------------- 3b. out = Wv' Z ----------------
__global__ void __launch_bounds__(256) gemm_out_kernel(float* __restrict__ Out) {
    __shared__ float As[64][64];
    __shared__ float Bs[64][128];
    int b = blockIdx.z, i0 = blockIdx.y * 64, n0 = blockIdx.x * 128, t = threadIdx.x;
    const float* Ap = g_Wv + i0 * CP;
#pragma unroll
    for (int j = 0; j < 4; j++) {
        int idx = t + j * 256, row = idx >> 4, c4 = idx & 15;
        *reinterpret_cast<float4*>(&As[row][c4 * 4]) =
            *reinterpret_cast<const float4*>(Ap + row * CP + c4 * 4);
    }
    const float* Bp = g_Z + (size_t)b * CP * NN + n0;
#pragma unroll
    for (int j = 0; j < 8; j++) {
        int idx = t + j * 256, row = idx >> 5, c4 = idx & 31;
        *reinterpret_cast<float4*>(&Bs[row][c4 * 4]) =
            *reinterpret_cast<const float4*>(Bp + row * NN + c4 * 4);
    }
    __syncthreads();
    int tx = t & 15, ty = t >> 4;
    float acc[4][8];
#pragma unroll
    for (int j = 0; j < 4; j++)
#pragma unroll
        for (int k = 0; k < 8; k++) acc[j][k] = 0.0f;
#pragma unroll 8
    for (int c = 0; c < 64; c++) {
        float a[4];
#pragma unroll
        for (int j = 0; j < 4; j++) a[j] = As[ty * 4 + j][c];
        float4 b0 = *reinterpret_cast<float4*>(&Bs[c][tx * 8]);
        float4 b1 = *reinterpret_cast<float4*>(&Bs[c][tx * 8 + 4]);
        float bb[8] = {b0.x, b0.y, b0.z, b0.w, b1.x, b1.y, b1.z, b1.w};
#pragma unroll
        for (int j = 0; j < 4; j++)
#pragma unroll
            for (int k = 0; k < 8; k++) acc[j][k] = fmaf(a[j], bb[k], acc[j][k]);
    }
    float* Op = Out + (size_t)b * DD * NN + n0;
#pragma unroll
    for (int j = 0; j < 4; j++) {
        int i = i0 + ty * 4 + j;
        *reinterpret_cast<float4*>(Op + (size_t)i * NN + tx * 8) =
            make_float4(acc[j][0], acc[j][1], acc[j][2], acc[j][3]);
        *reinterpret_cast<float4*>(Op + (size_t)i * NN + tx * 8 + 4) =
            make_float4(acc[j][4], acc[j][5], acc[j][6], acc[j][7]);
    }
}

// ---------------- 4. mma.sync fused flash attention, cp.async double-buffered ----------------
#define PITA 144                 // byte pitch for [.][c] tiles (64 bf16 + 8B pad)
#define PITK 272                 // byte pitch for K [c][m] tiles (128 bf16 + 8B pad)
#define SM_APEH 0
#define SM_APEL 18432
#define SM_STG  36864
#define OFF_UL  18432            // within a stage
#define OFF_KH  36864
#define OFF_KL  54272
#define SSTR    71680            // stage stride
#define SM_TOT  (SM_STG + 2 * SSTR)   // 180224

__device__ __forceinline__ void mma16816(float* d, const uint32_t* a, const uint32_t* b) {
    asm volatile("mma.sync.aligned.m16n8k16.row.col.f32.bf16.bf16.f32 "
        "{%0,%1,%2,%3}, {%4,%5,%6,%7}, {%8,%9}, {%0,%1,%2,%3};"
        : "+f"(d[0]), "+f"(d[1]), "+f"(d[2]), "+f"(d[3])
        : "r"(a[0]), "r"(a[1]), "r"(a[2]), "r"(a[3]), "r"(b[0]), "r"(b[1]));
}
__device__ __forceinline__ uint32_t pkbf(float lo, float hi) {
    __nv_bfloat16 h0 = __float2bfloat16(lo), h1 = __float2bfloat16(hi);
    return ((uint32_t)__bfloat16_as_ushort(h1) << 16) | __bfloat16_as_ushort(h0);
}

__global__ void __launch_bounds__(256, 1) fused_attn_mma() {
    extern __shared__ char smc[];
    uint32_t sb = smem_u32(smc);
    const int t = threadIdx.x, w = t >> 5, lane = t & 31;
    const int g = lane >> 2, tg = lane & 3;
    const int b = blockIdx.y, n0 = blockIdx.x * 128;

    // APE hi/lo (persistent)
    {
        const float4* sh = (const float4*)(g_An_hi + ((size_t)b * NN + n0) * CP);
        const float4* sl = (const float4*)(g_An_lo + ((size_t)b * NN + n0) * CP);
#pragma unroll
        for (int j = 0; j < 4; j++) {
            int li = t + j * 256, row = li >> 3, ch = li & 7;
            *(float4*)(smc + SM_APEH + row * PITA + ch * 16) = sh[li];
            *(float4*)(smc + SM_APEL + row * PITA + ch * 16) = sl[li];
        }
    }

    // issue one tile's U/K hi/lo via cp.async into stage s
    auto issue_tile = [&](int mt, int s) {
        int m0 = mt * 128;
        uint32_t ub = sb + SM_STG + s * SSTR;
#pragma unroll
        for (int j = 0; j < 4; j++) {
            int li = t + j * 256, row = li >> 3, ch = li & 7;
            cp16(ub + row * PITA + ch * 16,
                 g_U_hi + ((size_t)b * NN + m0 + row) * CP + ch * 8);
            cp16(ub + OFF_UL + row * PITA + ch * 16,
                 g_U_lo + ((size_t)b * NN + m0 + row) * CP + ch * 8);
        }
#pragma unroll
        for (int j = 0; j < 4; j++) {
            int li = t + j * 256, row = li >> 4, ch = li & 15;
            cp16(ub + OFF_KH + row * PITK + ch * 16,
                 g_Bk_hi + (size_t)(b * CP + row) * NN + m0 + ch * 8);
            cp16(ub + OFF_KL + row * PITK + ch * 16,
                 g_Bk_lo + (size_t)(b * CP + row) * NN + m0 + ch * 8);
        }
    };

    issue_tile(0, 0);
    CP_COMMIT();

    float zacc[8][4];
#pragma unroll
    for (int cf = 0; cf < 8; cf++)
#pragma unroll
        for (int e = 0; e < 4; e++) zacc[cf][e] = 0.0f;
    float mrun0 = -1e30f, mrun1 = -1e30f, lrun0 = 0.0f, lrun1 = 0.0f;

    for (int mt = 0; mt < 16; mt++) {
        if (mt < 15) { issue_tile(mt + 1, (mt + 1) & 1); CP_COMMIT(); CP_WAIT1(); }
        else CP_WAIT0();
        __syncthreads();

        const char* UB = smc + SM_STG + (size_t)(mt & 1) * SSTR;

        // ---- S = APE * U^T (3-term split) ----
        float sfr[16][4];
#pragma unroll
        for (int mf = 0; mf < 16; mf++)
#pragma unroll
            for (int e = 0; e < 4; e++) sfr[mf][e] = 0.0f;

#pragma unroll
        for (int ks = 0; ks < 4; ks++) {
            uint32_t abase = (uint32_t)((w * 16 + g) * PITA + (ks * 16 + tg * 2) * 2);
            uint32_t ah[4], al_[4];
            ah[0]  = *(const uint32_t*)(smc + SM_APEH + abase);
            ah[1]  = *(const uint32_t*)(smc + SM_APEH + abase + 8 * PITA);
            ah[2]  = *(const uint32_t*)(smc + SM_APEH + abase + 16);
            ah[3]  = *(const uint32_t*)(smc + SM_APEH + abase + 8 * PITA + 16);
            al_[0] = *(const uint32_t*)(smc + SM_APEL + abase);
            al_[1] = *(const uint32_t*)(smc + SM_APEL + abase + 8 * PITA);
            al_[2] = *(const uint32_t*)(smc + SM_APEL + abase + 16);
            al_[3] = *(const uint32_t*)(smc + SM_APEL + abase + 8 * PITA + 16);
#pragma unroll
            for (int mf = 0; mf < 16; mf++) {
                uint32_t bbase = (uint32_t)((mf * 8 + g) * PITA + (ks * 16 + tg * 2) * 2);
                uint32_t bh[2] = { *(const uint32_t*)(UB + bbase),
                                   *(const uint32_t*)(UB + bbase + 16) };
                uint32_t bl[2] = { *(const uint32_t*)(UB + OFF_UL + bbase),
                                   *(const uint32_t*)(UB + OFF_UL + bbase + 16) };
                mma16816(sfr[mf], ah, bh);
                mma16816(sfr[mf], ah, bl);
                mma16816(sfr[mf], al_, bh);
            }
        }

        // ---- online softmax ----
        float tm0 = -1e30f, tm1 = -1e30f;
#pragma unroll
        for (int mf = 0; mf < 16; mf++) {
            tm0 = fmaxf(tm0, fmaxf(sfr[mf][0], sfr[mf][1]));
            tm1 = fmaxf(tm1, fmaxf(sfr[mf][2], sfr[mf][3]));
        }
        tm0 = fmaxf(tm0, __shfl_xor_sync(0xffffffffu, tm0, 1));
        tm0 = fmaxf(tm0, __shfl_xor_sync(0xffffffffu, tm0, 2));
        tm1 = fmaxf(tm1, __shfl_xor_sync(0xffffffffu, tm1, 1));
        tm1 = fmaxf(tm1, __shfl_xor_sync(0xffffffffu, tm1, 2));
        float nm0 = fmaxf(mrun0, tm0), nm1 = fmaxf(mrun1, tm1);
        float al0 = __expf(mrun0 - nm0), al1 = __expf(mrun1 - nm1);
        mrun0 = nm0; mrun1 = nm1;
#pragma unroll
        for (int cf = 0; cf < 8; cf++) {
            zacc[cf][0] *= al0; zacc[cf][1] *= al0;
            zacc[cf][2] *= al1; zacc[cf][3] *= al1;
        }
        lrun0 *= al0; lrun1 *= al1;

        uint32_t ph[16][2], pl[16][2];
        float rs0 = 0.0f, rs1 = 0.0f;
#pragma unroll
        for (int mf = 0; mf < 16; mf++) {
            float p0 = __expf(sfr[mf][0] - nm0), p1 = __expf(sfr[mf][1] - nm0);
            float p2 = __expf(sfr[mf][2] - nm1), p3 = __expf(sfr[mf][3] - nm1);
            rs0 += p0 + p1; rs1 += p2 + p3;
            ph[mf][0] = pkbf(p0, p1);
            ph[mf][1] = pkbf(p2, p3);
            float q0 = p0 - __bfloat162float(__float2bfloat16(p0));
            float q1 = p1 - __bfloat162float(__float2bfloat16(p1));
            float q2 = p2 - __bfloat162float(__float2bfloat16(p2));
            float q3 = p3 - __bfloat162float(__float2bfloat16(p3));
            pl[mf][0] = pkbf(q0, q1);
            pl[mf][1] = pkbf(q2, q3);
        }
        rs0 += __shfl_xor_sync(0xffffffffu, rs0, 1);
        rs0 += __shfl_xor_sync(0xffffffffu, rs0, 2);
        rs1 += __shfl_xor_sync(0xffffffffu, rs1, 1);
        rs1 += __shfl_xor_sync(0xffffffffu, rs1, 2);
        lrun0 += rs0; lrun1 += rs1;

        // ---- Z += P * K^T (3-term split) ----
#pragma unroll
        for (int ks = 0; ks < 8; ks++) {
            uint32_t aph[4] = { ph[2 * ks][0], ph[2 * ks][1], ph[2 * ks + 1][0], ph[2 * ks + 1][1] };
            uint32_t apl[4] = { pl[2 * ks][0], pl[2 * ks][1], pl[2 * ks + 1][0], pl[2 * ks + 1][1] };
#pragma unroll
            for (int cf = 0; cf < 8; cf++) {
                uint32_t bb = (uint32_t)((cf * 8 + g) * PITK + (ks * 16 + tg * 2) * 2);
                uint32_t kh[2] = { *(const uint32_t*)(UB + OFF_KH + bb),
                                   *(const uint32_t*)(UB + OFF_KH + bb + 16) };
                uint32_t kl[2] = { *(const uint32_t*)(UB + OFF_KL + bb),
                                   *(const uint32_t*)(UB + OFF_KL + bb + 16) };
                mma16816(zacc[cf], aph, kh);
                mma16816(zacc[cf], apl, kh);
                mma16816(zacc[cf], aph, kl);
            }
        }
        __syncthreads();
    }

    // ---- epilogue ----
    float inv0 = 1.0f / lrun0, inv1 = 1.0f / lrun1;
    int nl0 = n0 + w * 16 + g, nl1 = nl0 + 8;
    float* Zb = g_Z + (size_t)b * CP * NN;
#pragma unroll
    for (int cf = 0; cf < 8; cf++) {
        int c0 = cf * 8 + tg * 2;
        Zb[(size_t)c0 * NN + nl0]       = zacc[cf][0] * inv0;
        Zb[(size_t)(c0 + 1) * NN + nl0] = zacc[cf][1] * inv0;
        Zb[(size_t)c0 * NN + nl1]       = zacc[cf][2] * inv1;
        Zb[(size_t)(c0 + 1) * NN + nl1] = zacc[cf][3] * inv1;
    }
}

// ---------------------------------------------------------------------------
extern "C" void kernel_launch(void* const* d_in, const int* in_sizes, int n_in,
                              void* d_out, int out_size) {
    const float* pos = (const float*)d_in[0];
    const float* Wq  = (const float*)d_in[1];
    const float* bq  = (const float*)d_in[2];
    const float* Wk  = (const float*)d_in[3];
    const float* bk  = (const float*)d_in[4];
    const float* Wv  = (const float*)d_in[5];
    const float* bv  = (const float*)d_in[6];
    float* out = (float*)d_out;

    pe_kernel<<<(BB * NN + 255) / 256, 256>>>(pos);
    prep_kernel<<<MBLK + WBLK, 256>>>(Wq, bq, Wk, bk, Wv, bv);
    gemm_u_kernel<<<dim3(NN / 128, 1, BB), 256>>>();

    cudaFuncSetAttribute(fused_attn_mma, cudaFuncAttributeMaxDynamicSharedMemorySize, SM_TOT);
    fused_attn_mma<<<dim3(NN / 128, BB), 256, SM_TOT>>>();

    gemm_out_kernel<<<dim3(NN / 128, DD / 64, BB), 256>>>(out);
}

// round 9
// speedup vs baseline: 2.1074x; 1.0626x over previous
#include <cuda_runtime.h>
#include <cuda_bf16.h>
#include <math.h>
#include <stdint.h>

#define BB 8
#define NN 2048
#define DD 384
#define CP 64
#define NF 10

__device__ float g_Z [BB * CP * NN];   // Z = pe' P^T / l
__device__ float g_M [CP * CP];        // padding stays 0 (zero-init, never written)
__device__ float g_Wv[DD * CP];
__device__ __nv_bfloat16 g_An_hi[BB * NN * CP];  // pe' transposed [b][n][c]
__device__ __nv_bfloat16 g_An_lo[BB * NN * CP];
__device__ __nv_bfloat16 g_U_hi [BB * NN * CP];  // u transposed [b][m][c]
__device__ __nv_bfloat16 g_U_lo [BB * NN * CP];
__device__ __nv_bfloat16 g_Bk_hi[BB * CP * NN];  // pe' natural [b][c][m]
__device__ __nv_bfloat16 g_Bk_lo[BB * CP * NN];

__device__ __forceinline__ uint32_t smem_u32(const void* p) {
    uint32_t a;
    asm("{ .reg .u64 t; cvta.to.shared.u64 t, %1; cvt.u32.u64 %0, t; }" : "=r"(a) : "l"(p));
    return a;
}
__device__ __forceinline__ void cp16(uint32_t dst, const void* src) {
    asm volatile("cp.async.cg.shared.global [%0], [%1], 16;" :: "r"(dst), "l"(src));
}
#define CP_COMMIT() asm volatile("cp.async.commit_group;" ::: "memory")
#define CP_WAIT1()  asm volatile("cp.async.wait_group 1;" ::: "memory")
#define CP_WAIT0()  asm volatile("cp.async.wait_group 0;" ::: "memory")

// pack two floats to bf16x2 (hi goes to upper 16 bits)
__device__ __forceinline__ uint32_t cvt2(float hi, float lo) {
    uint32_t r; asm("cvt.rn.bf16x2.f32 %0, %1, %2;" : "=r"(r) : "f"(hi), "f"(lo)); return r;
}

// ---------------- 1. prep: M' + Wv' ----------------
#define MOUT (61 * 61)
#define MBLK ((MOUT + 7) / 8)
#define WBLK ((DD * CP + 255) / 256)
__global__ void __launch_bounds__(256) prep_kernel(
        const float* __restrict__ Wq, const float* __restrict__ bq,
        const float* __restrict__ Wk, const float* __restrict__ bk,
        const float* __restrict__ Wv, const float* __restrict__ bv) {
    int t = threadIdx.x;
    if (blockIdx.x < MBLK) {
        int w = blockIdx.x * 8 + (t >> 5);
        if (w >= MOUT) return;
        int i = w / 61, j = w % 61, l = t & 31;
        float acc = 0.0f;
#pragma unroll
        for (int it = 0; it < 12; it++) {
            int d = l + it * 32;
            float aq = (i < 60) ? Wq[d * 60 + i] : bq[d];
            float ak = (j < 60) ? Wk[d * 60 + j] : bk[d];
            acc = fmaf(aq, ak, acc);
        }
#pragma unroll
        for (int s = 16; s > 0; s >>= 1) acc += __shfl_xor_sync(0xffffffffu, acc, s);
        if (l == 0) g_M[i * CP + j] = acc * sqrtf((float)DD);
    } else {
        int r = (blockIdx.x - MBLK) * 256 + t;
        if (r < DD * CP) {
            int d = r / CP, c = r % CP;
            g_Wv[r] = (c < 60) ? Wv[d * 60 + c] : ((c == 60) ? bv[d] : 0.0f);
        }
    }
}

// ---------------- 2. fused pe + splits + u-GEMM ----------------
// One block = 128 tokens. Computes pe tile in smem, emits An/Bk hi/lo splits,
// then u = M' pe and emits U hi/lo. g_pe never materialized.
#define BSP 132
__global__ void __launch_bounds__(256) pe_u_kernel(const float* __restrict__ pos) {
    __shared__ float Ms[64][64];
    __shared__ float Bs[64][BSP];
    int b = blockIdx.y, n0 = blockIdx.x * 128, t = threadIdx.x;

    // load M'
#pragma unroll
    for (int j = 0; j < 4; j++) {
        int idx = t + j * 256, row = idx >> 4, c4 = idx & 15;
        *reinterpret_cast<float4*>(&Ms[row][c4 * 4]) =
            *reinterpret_cast<const float4*>(g_M + row * CP + c4 * 4);
    }

    // pe phase: token tok = t>>1, half = t&1 computes 15 (coord,k) pairs
    {
        int tok = t >> 1, half = t & 1, n = n0 + tok;
        float x0 = pos[(size_t)b * 3 * NN + n];
        float x1 = pos[(size_t)b * 3 * NN + NN + n];
        float x2 = pos[(size_t)b * 3 * NN + 2 * NN + n];
#pragma unroll
        for (int pp = 0; pp < 15; pp++) {
            int p = 15 * half + pp;
            int coord = p / 10, k = p - coord * 10;
            float x = (coord == 0) ? x0 : ((coord == 1) ? x1 : x2);
            float s, c;
            sincosf(x * (float)(1 << k), &s, &c);
            Bs[coord * 20 + k][tok]      = s;
            Bs[coord * 20 + 10 + k][tok] = c;
        }
        if (half) {
            Bs[60][tok] = 1.0f; Bs[61][tok] = 0.0f;
            Bs[62][tok] = 0.0f; Bs[63][tok] = 0.0f;
        }
    }
    __syncthreads();

    // An hi/lo: thread t&127 = token, t>>7 selects hi vs lo array
    {
        int tk = t & 127, which = t >> 7;
        __nv_bfloat16 tmp[64];
        if (which == 0) {
#pragma unroll
            for (int c = 0; c < 64; c++) tmp[c] = __float2bfloat16(Bs[c][tk]);
        } else {
#pragma unroll
            for (int c = 0; c < 64; c++) {
                float x = Bs[c][tk];
                __nv_bfloat16 h = __float2bfloat16(x);
                tmp[c] = __float2bfloat16(x - __bfloat162float(h));
            }
        }
        float4* d = (float4*)((which ? g_An_lo : g_An_hi) + ((size_t)b * NN + n0 + tk) * CP);
#pragma unroll
        for (int j = 0; j < 8; j++) d[j] = ((float4*)tmp)[j];
    }

    // Bk hi/lo: coalesced bf16x2 stores
#pragma unroll
    for (int j = 0; j < 16; j++) {
        int idx = t + j * 256;
        int ch = idx >> 6, tp = idx & 63;
        float2 v = *reinterpret_cast<float2*>(&Bs[ch][tp * 2]);
        uint32_t hw = cvt2(v.y, v.x);
        float h0 = __uint_as_float(hw << 16);
        float h1 = __uint_as_float(hw & 0xffff0000u);
        uint32_t lw = cvt2(v.y - h1, v.x - h0);
        *reinterpret_cast<uint32_t*>(g_Bk_hi + ((size_t)b * CP + ch) * NN + n0 + tp * 2) = hw;
        *reinterpret_cast<uint32_t*>(g_Bk_lo + ((size_t)b * CP + ch) * NN + n0 + tp * 2) = lw;
    }

    // u = M' pe (64x128), write U hi/lo [m][c]
    int tx = t & 15, ty = t >> 4;
    float acc[4][8];
#pragma unroll
    for (int j = 0; j < 4; j++)
#pragma unroll
        for (int k = 0; k < 8; k++) acc[j][k] = 0.0f;
#pragma unroll 8
    for (int c = 0; c < 64; c++) {
        float a[4];
#pragma unroll
        for (int j = 0; j < 4; j++) a[j] = Ms[ty * 4 + j][c];
        float4 b0 = *reinterpret_cast<float4*>(&Bs[c][tx * 8]);
        float4 b1 = *reinterpret_cast<float4*>(&Bs[c][tx * 8 + 4]);
        float bb[8] = {b0.x, b0.y, b0.z, b0.w, b1.x, b1.y, b1.z, b1.w};
#pragma unroll
        for (int j = 0; j < 4; j++)
#pragma unroll
            for (int k = 0; k < 8; k++) acc[j][k] = fmaf(a[j], bb[k], acc[j][k]);
    }
#pragma unroll
    for (int k = 0; k < 8; k++) {
        size_t m = (size_t)b * NN + n0 + tx * 8 + k;
        uint32_t h01 = cvt2(acc[1][k], acc[0][k]);
        uint32_t h23 = cvt2(acc[3][k], acc[2][k]);
        float f0 = __uint_as_float(h01 << 16), f1 = __uint_as_float(h01 & 0xffff0000u);
        float f2 = __uint_as_float(h23 << 16), f3 = __uint_as_float(h23 & 0xffff0000u);
        uint32_t l01 = cvt2(acc[1][k] - f1, acc[0][k] - f0);
        uint32_t l23 = cvt2(acc[3][k] - f3, acc[2][k] - f2);
        *reinterpret_cast<uint2*>(g_U_hi + m * CP + ty * 4) = make_uint2(h01, h23);
        *reinterpret_cast<uint2*>(g_U_lo + m * CP + ty * 4) = make_uint2(l01, l23);
    }
}

// ---------------- 3. out = Wv' Z ----------------
__global__ void __launch_bounds__(256) gemm_out_kernel(float* __restrict__ Out) {
    __shared__ float As[64][64];
    __shared__ float Bs[64][128];
    int b = blockIdx.z, i0 = blockIdx.y * 64, n0 = blockIdx.x * 128, t = threadIdx.x;
    const float* Ap = g_Wv + i0 * CP;
#pragma unroll
    for (int j = 0; j < 4; j++) {
        int idx = t + j * 256, row = idx >> 4, c4 = idx & 15;
        *reinterpret_cast<float4*>(&As[row][c4 * 4]) =
            *reinterpret_cast<const float4*>(Ap + row * CP + c4 * 4);
    }
    const float* Bp = g_Z + (size_t)b * CP * NN + n0;
#pragma unroll
    for (int j = 0; j < 8; j++) {
        int idx = t + j * 256, row = idx >> 5, c4 = idx & 31;
        *reinterpret_cast<float4*>(&Bs[row][c4 * 4]) =
            *reinterpret_cast<const float4*>(Bp + row * NN + c4 * 4);
    }
    __syncthreads();
    int tx = t & 15, ty = t >> 4;
    float acc[4][8];
#pragma unroll
    for (int j = 0; j < 4; j++)
#pragma unroll
        for (int k = 0; k < 8; k++) acc[j][k] = 0.0f;
#pragma unroll 8
    for (int c = 0; c < 64; c++) {
        float a[4];
#pragma unroll
        for (int j = 0; j < 4; j++) a[j] = As[ty * 4 + j][c];
        float4 b0 = *reinterpret_cast<float4*>(&Bs[c][tx * 8]);
        float4 b1 = *reinterpret_cast<float4*>(&Bs[c][tx * 8 + 4]);
        float bb[8] = {b0.x, b0.y, b0.z, b0.w, b1.x, b1.y, b1.z, b1.w};
#pragma unroll
        for (int j = 0; j < 4; j++)
#pragma unroll
            for (int k = 0; k < 8; k++) acc[j][k] = fmaf(a[j], bb[k], acc[j][k]);
    }
    float* Op = Out + (size_t)b * DD * NN + n0;
#pragma unroll
    for (int j = 0; j < 4; j++) {
        int i = i0 + ty * 4 + j;
        *reinterpret_cast<float4*>(Op + (size_t)i * NN + tx * 8) =
            make_float4(acc[j][0], acc[j][1], acc[j][2], acc[j][3]);
        *reinterpret_cast<float4*>(Op + (size_t)i * NN + tx * 8 + 4) =
            make_float4(acc[j][4], acc[j][5], acc[j][6], acc[j][7]);
    }
}

// ---------------- 4. mma.sync fused flash attention ----------------
#define PITA 144
#define PITK 272
#define SM_APEH 0
#define SM_APEL 18432
#define SM_STG  36864
#define OFF_UL  18432
#define OFF_KH  36864
#define OFF_KL  54272
#define SSTR    71680
#define SM_TOT  (SM_STG + 2 * SSTR)

__device__ __forceinline__ void mma16816(float* d, const uint32_t* a, const uint32_t* b) {
    asm volatile("mma.sync.aligned.m16n8k16.row.col.f32.bf16.bf16.f32 "
        "{%0,%1,%2,%3}, {%4,%5,%6,%7}, {%8,%9}, {%0,%1,%2,%3};"
        : "+f"(d[0]), "+f"(d[1]), "+f"(d[2]), "+f"(d[3])
        : "r"(a[0]), "r"(a[1]), "r"(a[2]), "r"(a[3]), "r"(b[0]), "r"(b[1]));
}

__global__ void __launch_bounds__(256, 1) fused_attn_mma() {
    extern __shared__ char smc[];
    uint32_t sb = smem_u32(smc);
    const int t = threadIdx.x, w = t >> 5, lane = t & 31;
    const int g = lane >> 2, tg = lane & 3;
    const int b = blockIdx.y, n0 = blockIdx.x * 128;

    {
        const float4* sh = (const float4*)(g_An_hi + ((size_t)b * NN + n0) * CP);
        const float4* sl = (const float4*)(g_An_lo + ((size_t)b * NN + n0) * CP);
#pragma unroll
        for (int j = 0; j < 4; j++) {
            int li = t + j * 256, row = li >> 3, ch = li & 7;
            *(float4*)(smc + SM_APEH + row * PITA + ch * 16) = sh[li];
            *(float4*)(smc + SM_APEL + row * PITA + ch * 16) = sl[li];
        }
    }

    auto issue_tile = [&](int mt, int s) {
        int m0 = mt * 128;
        uint32_t ub = sb + SM_STG + s * SSTR;
#pragma unroll
        for (int j = 0; j < 4; j++) {
            int li = t + j * 256, row = li >> 3, ch = li & 7;
            cp16(ub + row * PITA + ch * 16,
                 g_U_hi + ((size_t)b * NN + m0 + row) * CP + ch * 8);
            cp16(ub + OFF_UL + row * PITA + ch * 16,
                 g_U_lo + ((size_t)b * NN + m0 + row) * CP + ch * 8);
        }
#pragma unroll
        for (int j = 0; j < 4; j++) {
            int li = t + j * 256, row = li >> 4, ch = li & 15;
            cp16(ub + OFF_KH + row * PITK + ch * 16,
                 g_Bk_hi + (size_t)(b * CP + row) * NN + m0 + ch * 8);
            cp16(ub + OFF_KL + row * PITK + ch * 16,
                 g_Bk_lo + (size_t)(b * CP + row) * NN + m0 + ch * 8);
        }
    };

    issue_tile(0, 0);
    CP_COMMIT();

    float zacc[8][4];
#pragma unroll
    for (int cf = 0; cf < 8; cf++)
#pragma unroll
        for (int e = 0; e < 4; e++) zacc[cf][e] = 0.0f;
    float mrun0 = -1e30f, mrun1 = -1e30f, lrun0 = 0.0f, lrun1 = 0.0f;

    for (int mt = 0; mt < 16; mt++) {
        if (mt < 15) { issue_tile(mt + 1, (mt + 1) & 1); CP_COMMIT(); CP_WAIT1(); }
        else CP_WAIT0();
        __syncthreads();

        const char* UB = smc + SM_STG + (size_t)(mt & 1) * SSTR;

        // ---- S = APE * U^T (3-term split) ----
        float sfr[16][4];
#pragma unroll
        for (int mf = 0; mf < 16; mf++)
#pragma unroll
            for (int e = 0; e < 4; e++) sfr[mf][e] = 0.0f;

#pragma unroll
        for (int ks = 0; ks < 4; ks++) {
            uint32_t abase = (uint32_t)((w * 16 + g) * PITA + (ks * 16 + tg * 2) * 2);
            uint32_t ah[4], al_[4];
            ah[0]  = *(const uint32_t*)(smc + SM_APEH + abase);
            ah[1]  = *(const uint32_t*)(smc + SM_APEH + abase + 8 * PITA);
            ah[2]  = *(const uint32_t*)(smc + SM_APEH + abase + 16);
            ah[3]  = *(const uint32_t*)(smc + SM_APEH + abase + 8 * PITA + 16);
            al_[0] = *(const uint32_t*)(smc + SM_APEL + abase);
            al_[1] = *(const uint32_t*)(smc + SM_APEL + abase + 8 * PITA);
            al_[2] = *(const uint32_t*)(smc + SM_APEL + abase + 16);
            al_[3] = *(const uint32_t*)(smc + SM_APEL + abase + 8 * PITA + 16);
#pragma unroll
            for (int mf = 0; mf < 16; mf++) {
                uint32_t bbase = (uint32_t)((mf * 8 + g) * PITA + (ks * 16 + tg * 2) * 2);
                uint32_t bh[2] = { *(const uint32_t*)(UB + bbase),
                                   *(const uint32_t*)(UB + bbase + 16) };
                uint32_t bl[2] = { *(const uint32_t*)(UB + OFF_UL + bbase),
                                   *(const uint32_t*)(UB + OFF_UL + bbase + 16) };
                mma16816(sfr[mf], ah, bh);
                mma16816(sfr[mf], ah, bl);
                mma16816(sfr[mf], al_, bh);
            }
        }

        // ---- online softmax ----
        float tm0 = -1e30f, tm1 = -1e30f;
#pragma unroll
        for (int mf = 0; mf < 16; mf++) {
            tm0 = fmaxf(tm0, fmaxf(sfr[mf][0], sfr[mf][1]));
            tm1 = fmaxf(tm1, fmaxf(sfr[mf][2], sfr[mf][3]));
        }
        tm0 = fmaxf(tm0, __shfl_xor_sync(0xffffffffu, tm0, 1));
        tm0 = fmaxf(tm0, __shfl_xor_sync(0xffffffffu, tm0, 2));
        tm1 = fmaxf(tm1, __shfl_xor_sync(0xffffffffu, tm1, 1));
        tm1 = fmaxf(tm1, __shfl_xor_sync(0xffffffffu, tm1, 2));
        float nm0 = fmaxf(mrun0, tm0), nm1 = fmaxf(mrun1, tm1);
        float al0 = __expf(mrun0 - nm0), al1 = __expf(mrun1 - nm1);
        mrun0 = nm0; mrun1 = nm1;
#pragma unroll
        for (int cf = 0; cf < 8; cf++) {
            zacc[cf][0] *= al0; zacc[cf][1] *= al0;
            zacc[cf][2] *= al1; zacc[cf][3] *= al1;
        }
        lrun0 *= al0; lrun1 *= al1;

        uint32_t ph[16][2], pl[16][2];
        float rs0 = 0.0f, rs1 = 0.0f;
#pragma unroll
        for (int mf = 0; mf < 16; mf++) {
            float p0 = __expf(sfr[mf][0] - nm0), p1 = __expf(sfr[mf][1] - nm0);
            float p2 = __expf(sfr[mf][2] - nm1), p3 = __expf(sfr[mf][3] - nm1);
            rs0 += p0 + p1; rs1 += p2 + p3;
            uint32_t h01 = cvt2(p1, p0);
            uint32_t h23 = cvt2(p3, p2);
            ph[mf][0] = h01; ph[mf][1] = h23;
            float f0 = __uint_as_float(h01 << 16), f1 = __uint_as_float(h01 & 0xffff0000u);
            float f2 = __uint_as_float(h23 << 16), f3 = __uint_as_float(h23 & 0xffff0000u);
            pl[mf][0] = cvt2(p1 - f1, p0 - f0);
            pl[mf][1] = cvt2(p3 - f3, p2 - f2);
        }
        rs0 += __shfl_xor_sync(0xffffffffu, rs0, 1);
        rs0 += __shfl_xor_sync(0xffffffffu, rs0, 2);
        rs1 += __shfl_xor_sync(0xffffffffu, rs1, 1);
        rs1 += __shfl_xor_sync(0xffffffffu, rs1, 2);
        lrun0 += rs0; lrun1 += rs1;

        // ---- Z += P * K^T (3-term split) ----
#pragma unroll
        for (int ks = 0; ks < 8; ks++) {
            uint32_t aph[4] = { ph[2 * ks][0], ph[2 * ks][1], ph[2 * ks + 1][0], ph[2 * ks + 1][1] };
            uint32_t apl[4] = { pl[2 * ks][0], pl[2 * ks][1], pl[2 * ks + 1][0], pl[2 * ks + 1][1] };
#pragma unroll
            for (int cf = 0; cf < 8; cf++) {
                uint32_t bb = (uint32_t)((cf * 8 + g) * PITK + (ks * 16 + tg * 2) * 2);
                uint32_t kh[2] = { *(const uint32_t*)(UB + OFF_KH + bb),
                                   *(const uint32_t*)(UB + OFF_KH + bb + 16) };
                uint32_t kl[2] = { *(const uint32_t*)(UB + OFF_KL + bb),
                                   *(const uint32_t*)(UB + OFF_KL + bb + 16) };
                mma16816(zacc[cf], aph, kh);
                mma16816(zacc[cf], apl, kh);
                mma16816(zacc[cf], aph, kl);
            }
        }
        __syncthreads();
    }

    // ---- epilogue ----
    float inv0 = 1.0f / lrun0, inv1 = 1.0f / lrun1;
    int nl0 = n0 + w * 16 + g, nl1 = nl0 + 8;
    float* Zb = g_Z + (size_t)b * CP * NN;
#pragma unroll
    for (int cf = 0; cf < 8; cf++) {
        int c0 = cf * 8 + tg * 2;
        Zb[(size_t)c0 * NN + nl0]       = zacc[cf][0] * inv0;
        Zb[(size_t)(c0 + 1) * NN + nl0] = zacc[cf][1] * inv0;
        Zb[(size_t)c0 * NN + nl1]       = zacc[cf][2] * inv1;
        Zb[(size_t)(c0 + 1) * NN + nl1] = zacc[cf][3] * inv1;
    }
}

// ---------------------------------------------------------------------------
extern "C" void kernel_launch(void* const* d_in, const int* in_sizes, int n_in,
                              void* d_out, int out_size) {
    const float* pos = (const float*)d_in[0];
    const float* Wq  = (const float*)d_in[1];
    const float* bq  = (const float*)d_in[2];
    const float* Wk  = (const float*)d_in[3];
    const float* bk  = (const float*)d_in[4];
    const float* Wv  = (const float*)d_in[5];
    const float* bv  = (const float*)d_in[6];
    float* out = (float*)d_out;

    prep_kernel<<<MBLK + WBLK, 256>>>(Wq, bq, Wk, bk, Wv, bv);
    pe_u_kernel<<<dim3(NN / 128, BB), 256>>>(pos);

    cudaFuncSetAttribute(fused_attn_mma, cudaFuncAttributeMaxDynamicSharedMemorySize, SM_TOT);
    fused_attn_mma<<<dim3(NN / 128, BB), 256, SM_TOT>>>();

    gemm_out_kernel<<<dim3(NN / 128, DD / 64, BB), 256>>>(out);
}

// round 10
// speedup vs baseline: 2.5093x; 1.1907x over previous
#include <cuda_runtime.h>
#include <cuda_bf16.h>
#include <math.h>
#include <stdint.h>

#define BB 8
#define NN 2048
#define DD 384
#define CP 64
#define NF 10

__device__ float g_M [CP * CP];        // padding stays 0 (zero-init, never written)
__device__ __nv_bfloat16 g_Wvh[DD * CP];         // Wv' hi  [d][c]
__device__ __nv_bfloat16 g_Wvl[DD * CP];         // Wv' lo
__device__ __nv_bfloat16 g_An_hi[BB * NN * CP];  // pe' transposed [b][n][c]
__device__ __nv_bfloat16 g_An_lo[BB * NN * CP];
__device__ __nv_bfloat16 g_U_hi [BB * NN * CP];  // u transposed [b][m][c]
__device__ __nv_bfloat16 g_U_lo [BB * NN * CP];
__device__ __nv_bfloat16 g_Bk_hi[BB * CP * NN];  // pe' natural [b][c][m]
__device__ __nv_bfloat16 g_Bk_lo[BB * CP * NN];
__device__ __nv_bfloat16 g_Zh[BB * NN * CP];     // Z/l hi [b][n][c]
__device__ __nv_bfloat16 g_Zl[BB * NN * CP];     // Z/l lo

__device__ __forceinline__ uint32_t smem_u32(const void* p) {
    uint32_t a;
    asm("{ .reg .u64 t; cvta.to.shared.u64 t, %1; cvt.u32.u64 %0, t; }" : "=r"(a) : "l"(p));
    return a;
}
__device__ __forceinline__ void cp16(uint32_t dst, const void* src) {
    asm volatile("cp.async.cg.shared.global [%0], [%1], 16;" :: "r"(dst), "l"(src));
}
#define CP_COMMIT() asm volatile("cp.async.commit_group;" ::: "memory")
#define CP_WAIT1()  asm volatile("cp.async.wait_group 1;" ::: "memory")
#define CP_WAIT0()  asm volatile("cp.async.wait_group 0;" ::: "memory")

__device__ __forceinline__ uint32_t cvt2(float hi, float lo) {
    uint32_t r; asm("cvt.rn.bf16x2.f32 %0, %1, %2;" : "=r"(r) : "f"(hi), "f"(lo)); return r;
}
__device__ __forceinline__ void mma16816(float* d, const uint32_t* a, const uint32_t* b) {
    asm volatile("mma.sync.aligned.m16n8k16.row.col.f32.bf16.bf16.f32 "
        "{%0,%1,%2,%3}, {%4,%5,%6,%7}, {%8,%9}, {%0,%1,%2,%3};"
        : "+f"(d[0]), "+f"(d[1]), "+f"(d[2]), "+f"(d[3])
        : "r"(a[0]), "r"(a[1]), "r"(a[2]), "r"(a[3]), "r"(b[0]), "r"(b[1]));
}

// ---------------- 1. prep: M' + Wv' (bf16 split) ----------------
#define MOUT (61 * 61)
#define MBLK ((MOUT + 7) / 8)
#define WBLK ((DD * CP + 255) / 256)
__global__ void __launch_bounds__(256) prep_kernel(
        const float* __restrict__ Wq, const float* __restrict__ bq,
        const float* __restrict__ Wk, const float* __restrict__ bk,
        const float* __restrict__ Wv, const float* __restrict__ bv) {
    int t = threadIdx.x;
    if (blockIdx.x < MBLK) {
        int w = blockIdx.x * 8 + (t >> 5);
        if (w >= MOUT) return;
        int i = w / 61, j = w % 61, l = t & 31;
        float acc = 0.0f;
#pragma unroll
        for (int it = 0; it < 12; it++) {
            int d = l + it * 32;
            float aq = (i < 60) ? Wq[d * 60 + i] : bq[d];
            float ak = (j < 60) ? Wk[d * 60 + j] : bk[d];
            acc = fmaf(aq, ak, acc);
        }
#pragma unroll
        for (int s = 16; s > 0; s >>= 1) acc += __shfl_xor_sync(0xffffffffu, acc, s);
        if (l == 0) g_M[i * CP + j] = acc * sqrtf((float)DD);
    } else {
        int r = (blockIdx.x - MBLK) * 256 + t;
        if (r < DD * CP) {
            int d = r / CP, c = r % CP;
            float v = (c < 60) ? Wv[d * 60 + c] : ((c == 60) ? bv[d] : 0.0f);
            __nv_bfloat16 h = __float2bfloat16(v);
            g_Wvh[r] = h;
            g_Wvl[r] = __float2bfloat16(v - __bfloat162float(h));
        }
    }
}

// ---------------- 2. fused pe + splits + u-GEMM ----------------
#define BSP 132
__global__ void __launch_bounds__(256) pe_u_kernel(const float* __restrict__ pos) {
    __shared__ float Ms[64][64];
    __shared__ float Bs[64][BSP];
    int b = blockIdx.y, n0 = blockIdx.x * 128, t = threadIdx.x;

#pragma unroll
    for (int j = 0; j < 4; j++) {
        int idx = t + j * 256, row = idx >> 4, c4 = idx & 15;
        *reinterpret_cast<float4*>(&Ms[row][c4 * 4]) =
            *reinterpret_cast<const float4*>(g_M + row * CP + c4 * 4);
    }
    {
        int tok = t >> 1, half = t & 1, n = n0 + tok;
        float x0 = pos[(size_t)b * 3 * NN + n];
        float x1 = pos[(size_t)b * 3 * NN + NN + n];
        float x2 = pos[(size_t)b * 3 * NN + 2 * NN + n];
#pragma unroll
        for (int pp = 0; pp < 15; pp++) {
            int p = 15 * half + pp;
            int coord = p / 10, k = p - coord * 10;
            float x = (coord == 0) ? x0 : ((coord == 1) ? x1 : x2);
            float s, c;
            sincosf(x * (float)(1 << k), &s, &c);
            Bs[coord * 20 + k][tok]      = s;
            Bs[coord * 20 + 10 + k][tok] = c;
        }
        if (half) {
            Bs[60][tok] = 1.0f; Bs[61][tok] = 0.0f;
            Bs[62][tok] = 0.0f; Bs[63][tok] = 0.0f;
        }
    }
    __syncthreads();

    {
        int tk = t & 127, which = t >> 7;
        __nv_bfloat16 tmp[64];
        if (which == 0) {
#pragma unroll
            for (int c = 0; c < 64; c++) tmp[c] = __float2bfloat16(Bs[c][tk]);
        } else {
#pragma unroll
            for (int c = 0; c < 64; c++) {
                float x = Bs[c][tk];
                __nv_bfloat16 h = __float2bfloat16(x);
                tmp[c] = __float2bfloat16(x - __bfloat162float(h));
            }
        }
        float4* d = (float4*)((which ? g_An_lo : g_An_hi) + ((size_t)b * NN + n0 + tk) * CP);
#pragma unroll
        for (int j = 0; j < 8; j++) d[j] = ((float4*)tmp)[j];
    }

#pragma unroll
    for (int j = 0; j < 16; j++) {
        int idx = t + j * 256;
        int ch = idx >> 6, tp = idx & 63;
        float2 v = *reinterpret_cast<float2*>(&Bs[ch][tp * 2]);
        uint32_t hw = cvt2(v.y, v.x);
        float h0 = __uint_as_float(hw << 16);
        float h1 = __uint_as_float(hw & 0xffff0000u);
        uint32_t lw = cvt2(v.y - h1, v.x - h0);
        *reinterpret_cast<uint32_t*>(g_Bk_hi + ((size_t)b * CP + ch) * NN + n0 + tp * 2) = hw;
        *reinterpret_cast<uint32_t*>(g_Bk_lo + ((size_t)b * CP + ch) * NN + n0 + tp * 2) = lw;
    }

    int tx = t & 15, ty = t >> 4;
    float acc[4][8];
#pragma unroll
    for (int j = 0; j < 4; j++)
#pragma unroll
        for (int k = 0; k < 8; k++) acc[j][k] = 0.0f;
#pragma unroll 8
    for (int c = 0; c < 64; c++) {
        float a[4];
#pragma unroll
        for (int j = 0; j < 4; j++) a[j] = Ms[ty * 4 + j][c];
        float4 b0 = *reinterpret_cast<float4*>(&Bs[c][tx * 8]);
        float4 b1 = *reinterpret_cast<float4*>(&Bs[c][tx * 8 + 4]);
        float bb[8] = {b0.x, b0.y, b0.z, b0.w, b1.x, b1.y, b1.z, b1.w};
#pragma unroll
        for (int j = 0; j < 4; j++)
#pragma unroll
            for (int k = 0; k < 8; k++) acc[j][k] = fmaf(a[j], bb[k], acc[j][k]);
    }
#pragma unroll
    for (int k = 0; k < 8; k++) {
        size_t m = (size_t)b * NN + n0 + tx * 8 + k;
        uint32_t h01 = cvt2(acc[1][k], acc[0][k]);
        uint32_t h23 = cvt2(acc[3][k], acc[2][k]);
        float f0 = __uint_as_float(h01 << 16), f1 = __uint_as_float(h01 & 0xffff0000u);
        float f2 = __uint_as_float(h23 << 16), f3 = __uint_as_float(h23 & 0xffff0000u);
        uint32_t l01 = cvt2(acc[1][k] - f1, acc[0][k] - f0);
        uint32_t l23 = cvt2(acc[3][k] - f3, acc[2][k] - f2);
        *reinterpret_cast<uint2*>(g_U_hi + m * CP + ty * 4) = make_uint2(h01, h23);
        *reinterpret_cast<uint2*>(g_U_lo + m * CP + ty * 4) = make_uint2(l01, l23);
    }
}

// ---------------- 3. mma.sync fused flash attention ----------------
#define PITA 144
#define PITK 272
#define SM_APEH 0
#define SM_APEL 18432
#define SM_STG  36864
#define OFF_UL  18432
#define OFF_KH  36864
#define OFF_KL  54272
#define SSTR    71680
#define SM_TOT  (SM_STG + 2 * SSTR)

__global__ void __launch_bounds__(256, 1) fused_attn_mma() {
    extern __shared__ char smc[];
    uint32_t sb = smem_u32(smc);
    const int t = threadIdx.x, w = t >> 5, lane = t & 31;
    const int g = lane >> 2, tg = lane & 3;
    const int b = blockIdx.y, n0 = blockIdx.x * 128;

    {
        const float4* sh = (const float4*)(g_An_hi + ((size_t)b * NN + n0) * CP);
        const float4* sl = (const float4*)(g_An_lo + ((size_t)b * NN + n0) * CP);
#pragma unroll
        for (int j = 0; j < 4; j++) {
            int li = t + j * 256, row = li >> 3, ch = li & 7;
            *(float4*)(smc + SM_APEH + row * PITA + ch * 16) = sh[li];
            *(float4*)(smc + SM_APEL + row * PITA + ch * 16) = sl[li];
        }
    }

    auto issue_tile = [&](int mt, int s) {
        int m0 = mt * 128;
        uint32_t ub = sb + SM_STG + s * SSTR;
#pragma unroll
        for (int j = 0; j < 4; j++) {
            int li = t + j * 256, row = li >> 3, ch = li & 7;
            cp16(ub + row * PITA + ch * 16,
                 g_U_hi + ((size_t)b * NN + m0 + row) * CP + ch * 8);
            cp16(ub + OFF_UL + row * PITA + ch * 16,
                 g_U_lo + ((size_t)b * NN + m0 + row) * CP + ch * 8);
        }
#pragma unroll
        for (int j = 0; j < 4; j++) {
            int li = t + j * 256, row = li >> 4, ch = li & 15;
            cp16(ub + OFF_KH + row * PITK + ch * 16,
                 g_Bk_hi + (size_t)(b * CP + row) * NN + m0 + ch * 8);
            cp16(ub + OFF_KL + row * PITK + ch * 16,
                 g_Bk_lo + (size_t)(b * CP + row) * NN + m0 + ch * 8);
        }
    };

    issue_tile(0, 0);
    CP_COMMIT();

    float zacc[8][4];
#pragma unroll
    for (int cf = 0; cf < 8; cf++)
#pragma unroll
        for (int e = 0; e < 4; e++) zacc[cf][e] = 0.0f;
    float mrun0 = -1e30f, mrun1 = -1e30f, lrun0 = 0.0f, lrun1 = 0.0f;

    for (int mt = 0; mt < 16; mt++) {
        if (mt < 15) { issue_tile(mt + 1, (mt + 1) & 1); CP_COMMIT(); CP_WAIT1(); }
        else CP_WAIT0();
        __syncthreads();

        const char* UB = smc + SM_STG + (size_t)(mt & 1) * SSTR;

        float sfr[16][4];
#pragma unroll
        for (int mf = 0; mf < 16; mf++)
#pragma unroll
            for (int e = 0; e < 4; e++) sfr[mf][e] = 0.0f;

#pragma unroll
        for (int ks = 0; ks < 4; ks++) {
            uint32_t abase = (uint32_t)((w * 16 + g) * PITA + (ks * 16 + tg * 2) * 2);
            uint32_t ah[4], al_[4];
            ah[0]  = *(const uint32_t*)(smc + SM_APEH + abase);
            ah[1]  = *(const uint32_t*)(smc + SM_APEH + abase + 8 * PITA);
            ah[2]  = *(const uint32_t*)(smc + SM_APEH + abase + 16);
            ah[3]  = *(const uint32_t*)(smc + SM_APEH + abase + 8 * PITA + 16);
            al_[0] = *(const uint32_t*)(smc + SM_APEL + abase);
            al_[1] = *(const uint32_t*)(smc + SM_APEL + abase + 8 * PITA);
            al_[2] = *(const uint32_t*)(smc + SM_APEL + abase + 16);
            al_[3] = *(const uint32_t*)(smc + SM_APEL + abase + 8 * PITA + 16);
#pragma unroll
            for (int mf = 0; mf < 16; mf++) {
                uint32_t bbase = (uint32_t)((mf * 8 + g) * PITA + (ks * 16 + tg * 2) * 2);
                uint32_t bh[2] = { *(const uint32_t*)(UB + bbase),
                                   *(const uint32_t*)(UB + bbase + 16) };
                uint32_t bl[2] = { *(const uint32_t*)(UB + OFF_UL + bbase),
                                   *(const uint32_t*)(UB + OFF_UL + bbase + 16) };
                mma16816(sfr[mf], ah, bh);
                mma16816(sfr[mf], ah, bl);
                mma16816(sfr[mf], al_, bh);
            }
        }

        float tm0 = -1e30f, tm1 = -1e30f;
#pragma unroll
        for (int mf = 0; mf < 16; mf++) {
            tm0 = fmaxf(tm0, fmaxf(sfr[mf][0], sfr[mf][1]));
            tm1 = fmaxf(tm1, fmaxf(sfr[mf][2], sfr[mf][3]));
        }
        tm0 = fmaxf(tm0, __shfl_xor_sync(0xffffffffu, tm0, 1));
        tm0 = fmaxf(tm0, __shfl_xor_sync(0xffffffffu, tm0, 2));
        tm1 = fmaxf(tm1, __shfl_xor_sync(0xffffffffu, tm1, 1));
        tm1 = fmaxf(tm1, __shfl_xor_sync(0xffffffffu, tm1, 2));
        float nm0 = fmaxf(mrun0, tm0), nm1 = fmaxf(mrun1, tm1);
        float al0 = __expf(mrun0 - nm0), al1 = __expf(mrun1 - nm1);
        mrun0 = nm0; mrun1 = nm1;
#pragma unroll
        for (int cf = 0; cf < 8; cf++) {
            zacc[cf][0] *= al0; zacc[cf][1] *= al0;
            zacc[cf][2] *= al1; zacc[cf][3] *= al1;
        }
        lrun0 *= al0; lrun1 *= al1;

        uint32_t ph[16][2], pl[16][2];
        float rs0 = 0.0f, rs1 = 0.0f;
#pragma unroll
        for (int mf = 0; mf < 16; mf++) {
            float p0 = __expf(sfr[mf][0] - nm0), p1 = __expf(sfr[mf][1] - nm0);
            float p2 = __expf(sfr[mf][2] - nm1), p3 = __expf(sfr[mf][3] - nm1);
            rs0 += p0 + p1; rs1 += p2 + p3;
            uint32_t h01 = cvt2(p1, p0);
            uint32_t h23 = cvt2(p3, p2);
            ph[mf][0] = h01; ph[mf][1] = h23;
            float f0 = __uint_as_float(h01 << 16), f1 = __uint_as_float(h01 & 0xffff0000u);
            float f2 = __uint_as_float(h23 << 16), f3 = __uint_as_float(h23 & 0xffff0000u);
            pl[mf][0] = cvt2(p1 - f1, p0 - f0);
            pl[mf][1] = cvt2(p3 - f3, p2 - f2);
        }
        rs0 += __shfl_xor_sync(0xffffffffu, rs0, 1);
        rs0 += __shfl_xor_sync(0xffffffffu, rs0, 2);
        rs1 += __shfl_xor_sync(0xffffffffu, rs1, 1);
        rs1 += __shfl_xor_sync(0xffffffffu, rs1, 2);
        lrun0 += rs0; lrun1 += rs1;

#pragma unroll
        for (int ks = 0; ks < 8; ks++) {
            uint32_t aph[4] = { ph[2 * ks][0], ph[2 * ks][1], ph[2 * ks + 1][0], ph[2 * ks + 1][1] };
            uint32_t apl[4] = { pl[2 * ks][0], pl[2 * ks][1], pl[2 * ks + 1][0], pl[2 * ks + 1][1] };
#pragma unroll
            for (int cf = 0; cf < 8; cf++) {
                uint32_t bb = (uint32_t)((cf * 8 + g) * PITK + (ks * 16 + tg * 2) * 2);
                uint32_t kh[2] = { *(const uint32_t*)(UB + OFF_KH + bb),
                                   *(const uint32_t*)(UB + OFF_KH + bb + 16) };
                uint32_t kl[2] = { *(const uint32_t*)(UB + OFF_KL + bb),
                                   *(const uint32_t*)(UB + OFF_KL + bb + 16) };
                mma16816(zacc[cf], aph, kh);
                mma16816(zacc[cf], apl, kh);
                mma16816(zacc[cf], aph, kl);
            }
        }
        __syncthreads();
    }

    // ---- epilogue: normalize, split to bf16 hi/lo, write Z [n][c] ----
    float inv0 = 1.0f / lrun0, inv1 = 1.0f / lrun1;
    int nl0 = n0 + w * 16 + g, nl1 = nl0 + 8;
    __nv_bfloat16* Zh0 = g_Zh + ((size_t)b * NN + nl0) * CP;
    __nv_bfloat16* Zl0 = g_Zl + ((size_t)b * NN + nl0) * CP;
    __nv_bfloat16* Zh1 = g_Zh + ((size_t)b * NN + nl1) * CP;
    __nv_bfloat16* Zl1 = g_Zl + ((size_t)b * NN + nl1) * CP;
#pragma unroll
    for (int cf = 0; cf < 8; cf++) {
        int c0 = cf * 8 + tg * 2;
        float v0 = zacc[cf][0] * inv0, v1 = zacc[cf][1] * inv0;
        float v2 = zacc[cf][2] * inv1, v3 = zacc[cf][3] * inv1;
        uint32_t h01 = cvt2(v1, v0);
        uint32_t h23 = cvt2(v3, v2);
        float f0 = __uint_as_float(h01 << 16), f1 = __uint_as_float(h01 & 0xffff0000u);
        float f2 = __uint_as_float(h23 << 16), f3 = __uint_as_float(h23 & 0xffff0000u);
        *reinterpret_cast<uint32_t*>(Zh0 + c0) = h01;
        *reinterpret_cast<uint32_t*>(Zl0 + c0) = cvt2(v1 - f1, v0 - f0);
        *reinterpret_cast<uint32_t*>(Zh1 + c0) = h23;
        *reinterpret_cast<uint32_t*>(Zl1 + c0) = cvt2(v3 - f3, v2 - f2);
    }
}

// ---------------- 4. tensor-core output GEMM: out = Wv' Z ----------------
#define GP_WVH 0
#define GP_WVL 18432
#define GP_ZH  36864
#define GP_ZL  55296
#define GP_TOT 73728

__global__ void __launch_bounds__(256, 1) gemm_out_tc(float* __restrict__ Out) {
    extern __shared__ char sm2[];
    int b = blockIdx.z, d0 = blockIdx.y * 128, n0 = blockIdx.x * 128;
    int t = threadIdx.x, w = t >> 5, lane = t & 31;
    int g = lane >> 2, tg = lane & 3;

#pragma unroll
    for (int j = 0; j < 4; j++) {
        int li = t + j * 256, row = li >> 3, ch = li & 7;
        *(float4*)(sm2 + GP_WVH + row * PITA + ch * 16) =
            *(const float4*)(g_Wvh + (size_t)(d0 + row) * CP + ch * 8);
        *(float4*)(sm2 + GP_WVL + row * PITA + ch * 16) =
            *(const float4*)(g_Wvl + (size_t)(d0 + row) * CP + ch * 8);
        *(float4*)(sm2 + GP_ZH + row * PITA + ch * 16) =
            *(const float4*)(g_Zh + ((size_t)b * NN + n0 + row) * CP + ch * 8);
        *(float4*)(sm2 + GP_ZL + row * PITA + ch * 16) =
            *(const float4*)(g_Zl + ((size_t)b * NN + n0 + row) * CP + ch * 8);
    }
    __syncthreads();

    float acc[16][4];
#pragma unroll
    for (int nf = 0; nf < 16; nf++)
#pragma unroll
        for (int e = 0; e < 4; e++) acc[nf][e] = 0.0f;

#pragma unroll
    for (int ks = 0; ks < 4; ks++) {
        uint32_t abase = (uint32_t)((w * 16 + g) * PITA + (ks * 16 + tg * 2) * 2);
        uint32_t ah[4], al_[4];
        ah[0]  = *(const uint32_t*)(sm2 + GP_WVH + abase);
        ah[1]  = *(const uint32_t*)(sm2 + GP_WVH + abase + 8 * PITA);
        ah[2]  = *(const uint32_t*)(sm2 + GP_WVH + abase + 16);
        ah[3]  = *(const uint32_t*)(sm2 + GP_WVH + abase + 8 * PITA + 16);
        al_[0] = *(const uint32_t*)(sm2 + GP_WVL + abase);
        al_[1] = *(const uint32_t*)(sm2 + GP_WVL + abase + 8 * PITA);
        al_[2] = *(const uint32_t*)(sm2 + GP_WVL + abase + 16);
        al_[3] = *(const uint32_t*)(sm2 + GP_WVL + abase + 8 * PITA + 16);
#pragma unroll
        for (int nf = 0; nf < 16; nf++) {
            uint32_t bbase = (uint32_t)((nf * 8 + g) * PITA + (ks * 16 + tg * 2) * 2);
            uint32_t bh[2] = { *(const uint32_t*)(sm2 + GP_ZH + bbase),
                               *(const uint32_t*)(sm2 + GP_ZH + bbase + 16) };
            uint32_t bl[2] = { *(const uint32_t*)(sm2 + GP_ZL + bbase),
                               *(const uint32_t*)(sm2 + GP_ZL + bbase + 16) };
            mma16816(acc[nf], ah, bh);
            mma16816(acc[nf], ah, bl);
            mma16816(acc[nf], al_, bh);
        }
    }

    float* Op = Out + (size_t)b * DD * NN;
    int dd0 = d0 + w * 16 + g, dd1 = dd0 + 8;
#pragma unroll
    for (int nf = 0; nf < 16; nf++) {
        int n = n0 + nf * 8 + tg * 2;
        *reinterpret_cast<float2*>(Op + (size_t)dd0 * NN + n) = make_float2(acc[nf][0], acc[nf][1]);
        *reinterpret_cast<float2*>(Op + (size_t)dd1 * NN + n) = make_float2(acc[nf][2], acc[nf][3]);
    }
}

// ---------------------------------------------------------------------------
extern "C" void kernel_launch(void* const* d_in, const int* in_sizes, int n_in,
                              void* d_out, int out_size) {
    const float* pos = (const float*)d_in[0];
    const float* Wq  = (const float*)d_in[1];
    const float* bq  = (const float*)d_in[2];
    const float* Wk  = (const float*)d_in[3];
    const float* bk  = (const float*)d_in[4];
    const float* Wv  = (const float*)d_in[5];
    const float* bv  = (const float*)d_in[6];
    float* out = (float*)d_out;

    prep_kernel<<<MBLK + WBLK, 256>>>(Wq, bq, Wk, bk, Wv, bv);
    pe_u_kernel<<<dim3(NN / 128, BB), 256>>>(pos);

    cudaFuncSetAttribute(fused_attn_mma, cudaFuncAttributeMaxDynamicSharedMemorySize, SM_TOT);
    fused_attn_mma<<<dim3(NN / 128, BB), 256, SM_TOT>>>();

    cudaFuncSetAttribute(gemm_out_tc, cudaFuncAttributeMaxDynamicSharedMemorySize, GP_TOT);
    gemm_out_tc<<<dim3(NN / 128, DD / 128, BB), 256, GP_TOT>>>(out);
}